// round 5
// baseline (speedup 1.0000x reference)
#include <cuda_runtime.h>
#include <cuda_bf16.h>
#include <cstdint>

// Problem constants
#define Bn  2
#define Tn  2048
#define En  1024
#define NHn 16
#define HSn 64
#define Mn  (Bn * Tn)        // 4096 token rows

// ---------------- scratch (device globals; no allocation) ----------------
__device__ __nv_bfloat16 g_Xh[(size_t)Mn * En];
__device__ __nv_bfloat16 g_Xl[(size_t)Mn * En];
__device__ __nv_bfloat16 g_Wqh[(size_t)En * En];
__device__ __nv_bfloat16 g_Wql[(size_t)En * En];
__device__ __nv_bfloat16 g_Wkh[(size_t)En * En];
__device__ __nv_bfloat16 g_Wkl[(size_t)En * En];
__device__ __nv_bfloat16 g_Wvh[(size_t)En * En];
__device__ __nv_bfloat16 g_Wvl[(size_t)En * En];
__device__ __nv_bfloat16 g_Woh[(size_t)En * En];
__device__ __nv_bfloat16 g_Wol[(size_t)En * En];
__device__ __nv_bfloat16 g_Qh[(size_t)Mn * En];
__device__ __nv_bfloat16 g_Ql[(size_t)Mn * En];
__device__ __nv_bfloat16 g_Kh[(size_t)Mn * En];
__device__ __nv_bfloat16 g_Kl[(size_t)Mn * En];
__device__ __nv_bfloat16 g_Vh[(size_t)Mn * En];
__device__ __nv_bfloat16 g_Vl[(size_t)Mn * En];
__device__ __nv_bfloat16 g_Ah[(size_t)Mn * En];
__device__ __nv_bfloat16 g_Al[(size_t)Mn * En];

// =====================================================================
// Baseline-PTX helpers (valid on compute_103 virtual arch)
// =====================================================================
__device__ __forceinline__ uint32_t smem_u32(const void* p) {
    uint32_t a;
    asm("{ .reg .u64 t; cvta.to.shared.u64 t, %1; cvt.u32.u64 %0, t; }"
        : "=r"(a) : "l"(p));
    return a;
}

__device__ __forceinline__ void mma_bf16(float* d, const uint32_t* a,
                                         const uint32_t* b) {
    asm volatile(
        "mma.sync.aligned.m16n8k16.row.col.f32.bf16.bf16.f32 "
        "{%0,%1,%2,%3}, {%4,%5,%6,%7}, {%8,%9}, {%0,%1,%2,%3};\n"
        : "+f"(d[0]), "+f"(d[1]), "+f"(d[2]), "+f"(d[3])
        : "r"(a[0]), "r"(a[1]), "r"(a[2]), "r"(a[3]), "r"(b[0]), "r"(b[1]));
}

__device__ __forceinline__ void ldsm_x4(uint32_t* r, uint32_t a) {
    asm volatile("ldmatrix.sync.aligned.m8n8.x4.shared.b16 {%0,%1,%2,%3}, [%4];"
                 : "=r"(r[0]), "=r"(r[1]), "=r"(r[2]), "=r"(r[3]) : "r"(a));
}
__device__ __forceinline__ void ldsm_x4_t(uint32_t* r, uint32_t a) {
    asm volatile("ldmatrix.sync.aligned.m8n8.x4.trans.shared.b16 {%0,%1,%2,%3}, [%4];"
                 : "=r"(r[0]), "=r"(r[1]), "=r"(r[2]), "=r"(r[3]) : "r"(a));
}

__device__ __forceinline__ void cp16(uint32_t d, const void* g) {
    asm volatile("cp.async.cg.shared.global [%0], [%1], 16;" :: "r"(d), "l"(g));
}
#define CP_COMMIT() asm volatile("cp.async.commit_group;" ::: "memory")
#define CP_WAIT0()  asm volatile("cp.async.wait_group 0;" ::: "memory")
#define CP_WAIT1()  asm volatile("cp.async.wait_group 1;" ::: "memory")

__device__ __forceinline__ uint32_t packbf(float a, float b) {
    __nv_bfloat162 t = __floats2bfloat162_rn(a, b);   // .x = a -> low bits
    return *reinterpret_cast<uint32_t*>(&t);
}
__device__ __forceinline__ uint32_t pack2h(__nv_bfloat16 a, __nv_bfloat16 b) {
    __nv_bfloat162 t(a, b);
    return *reinterpret_cast<uint32_t*>(&t);
}

// =====================================================================
// Fused split kernel: one launch splits X + all 4 weights into bf16 hi/lo.
// =====================================================================
__global__ void __launch_bounds__(256) split_all(
    const float* __restrict__ X,  const float* __restrict__ Wq,
    const float* __restrict__ Wk, const float* __restrict__ Wv,
    const float* __restrict__ Wo)
{
    const int i = blockIdx.x * blockDim.x + threadIdx.x;   // float4 index
    const float* src; __nv_bfloat16 *hi, *lo; int base;
    if (i < (1 << 20)) {
        src = X; hi = g_Xh; lo = g_Xl; base = i;
    } else {
        const int r = i - (1 << 20);
        const int seg = r >> 18;
        base = r & ((1 << 18) - 1);
        switch (seg) {
            case 0:  src = Wq; hi = g_Wqh; lo = g_Wql; break;
            case 1:  src = Wk; hi = g_Wkh; lo = g_Wkl; break;
            case 2:  src = Wv; hi = g_Wvh; lo = g_Wvl; break;
            default: src = Wo; hi = g_Woh; lo = g_Wol; break;
        }
    }
    const float4 v = *(const float4*)(src + (size_t)base * 4);
    const __nv_bfloat16 h0 = __float2bfloat16(v.x), h1 = __float2bfloat16(v.y);
    const __nv_bfloat16 h2 = __float2bfloat16(v.z), h3 = __float2bfloat16(v.w);
    uint2 hh, ll;
    hh.x = pack2h(h0, h1);
    hh.y = pack2h(h2, h3);
    ll.x = packbf(v.x - __bfloat162float(h0), v.y - __bfloat162float(h1));
    ll.y = packbf(v.z - __bfloat162float(h2), v.w - __bfloat162float(h3));
    *(uint2*)(hi + (size_t)base * 4) = hh;
    *(uint2*)(lo + (size_t)base * 4) = ll;
}

// =====================================================================
// GEMM: C[128x128] = A[4096xK] * W^T + bias, bf16x3 via mma.sync.
// 256 thr, 8 warps (4m x 2n), k-stage 32, cp.async double buffer.
// 2 CTAs/SM (launch_bounds) -> 16 warps interleave across CTAs.
// =====================================================================
#define GTILE  (128 * 80)      // one [128 x 32] bf16 tile (padded)
#define GSTAGE (4 * GTILE)     // Ah, Al, Bh, Bl
#define GEMM_SMEM (2 * GSTAGE) // 81920

__device__ __forceinline__ void gemm_prefetch(
    uint32_t sbs, const __nv_bfloat16* pA0, const __nv_bfloat16* pA1,
    const __nv_bfloat16* pB0, const __nv_bfloat16* pB1, int k0, int tid)
{
    #pragma unroll
    for (int t = 0; t < 4; t++) {
        const __nv_bfloat16* s = (t == 0) ? pA0 : (t == 1) ? pA1
                               : (t == 2) ? pB0 : pB1;
        #pragma unroll
        for (int i = 0; i < 2; i++) {
            int cc  = i * 256 + tid;       // 0..511
            int row = cc >> 2, seg = cc & 3;
            cp16(sbs + t * GTILE + row * 80 + seg * 16,
                 s + (size_t)row * En + k0 + seg * 8);
        }
    }
}

__device__ __forceinline__ void gemm_core(
    const __nv_bfloat16* __restrict__ Ah, const __nv_bfloat16* __restrict__ Al,
    const __nv_bfloat16* __restrict__ Bh, const __nv_bfloat16* __restrict__ Bl,
    const float* __restrict__ bias, float* __restrict__ outF,
    __nv_bfloat16* __restrict__ outH, __nv_bfloat16* __restrict__ outL,
    float outScale)
{
    extern __shared__ char smc[];
    const uint32_t sb = smem_u32(smc);
    const int tid = threadIdx.x, lane = tid & 31, wid = tid >> 5;
    const int wm = wid & 3, wn = wid >> 2;
    const int rowBase = blockIdx.y * 128, colBase = blockIdx.x * 128;

    const __nv_bfloat16* pA0 = Ah + (size_t)rowBase * En;
    const __nv_bfloat16* pA1 = Al + (size_t)rowBase * En;
    const __nv_bfloat16* pB0 = Bh + (size_t)colBase * En;
    const __nv_bfloat16* pB1 = Bl + (size_t)colBase * En;

    float acc[2][8][4];
    #pragma unroll
    for (int i = 0; i < 2; i++)
        #pragma unroll
        for (int j = 0; j < 8; j++)
            #pragma unroll
            for (int e = 0; e < 4; e++) acc[i][j][e] = 0.f;

    gemm_prefetch(sb, pA0, pA1, pB0, pB1, 0, tid);
    CP_COMMIT();

    const uint32_t aoff = (lane & 15) * 80 + (lane >> 4) * 16;
    const uint32_t boff = (((lane & 16) >> 1) + (lane & 7)) * 80
                        + ((lane & 8) ? 16 : 0);

    for (int st = 0; st < En / 32; st++) {
        if (st + 1 < En / 32) {
            gemm_prefetch(sb + ((st + 1) & 1) * GSTAGE,
                          pA0, pA1, pB0, pB1, (st + 1) * 32, tid);
            CP_COMMIT();
            CP_WAIT1();
        } else {
            CP_WAIT0();
        }
        __syncthreads();
        const uint32_t s0 = sb + (st & 1) * GSTAGE;
        const uint32_t aH = s0, aL = s0 + GTILE, bH = s0 + 2 * GTILE,
                       bL = s0 + 3 * GTILE;

        #pragma unroll
        for (int kk = 0; kk < 2; kk++) {
            uint32_t ah[2][4], al[2][4], bh4[4][4], bl4[4][4];
            #pragma unroll
            for (int mi = 0; mi < 2; mi++) {
                const uint32_t r = (wm * 32 + mi * 16) * 80 + aoff + kk * 32;
                ldsm_x4(ah[mi], aH + r);
                ldsm_x4(al[mi], aL + r);
            }
            #pragma unroll
            for (int n4 = 0; n4 < 4; n4++) {
                const uint32_t r = (wn * 64 + n4 * 16) * 80 + boff + kk * 32;
                ldsm_x4(bh4[n4], bH + r);
                ldsm_x4(bl4[n4], bL + r);
            }
            // 3 independent passes: 16 independent acc chains per pass
            #pragma unroll
            for (int mi = 0; mi < 2; mi++)
                #pragma unroll
                for (int nj = 0; nj < 8; nj++)
                    mma_bf16(acc[mi][nj], ah[mi], &bh4[nj >> 1][(nj & 1) * 2]);
            #pragma unroll
            for (int mi = 0; mi < 2; mi++)
                #pragma unroll
                for (int nj = 0; nj < 8; nj++)
                    mma_bf16(acc[mi][nj], ah[mi], &bl4[nj >> 1][(nj & 1) * 2]);
            #pragma unroll
            for (int mi = 0; mi < 2; mi++)
                #pragma unroll
                for (int nj = 0; nj < 8; nj++)
                    mma_bf16(acc[mi][nj], al[mi], &bh4[nj >> 1][(nj & 1) * 2]);
        }
        __syncthreads();
    }

    // epilogue
    #pragma unroll
    for (int mi = 0; mi < 2; mi++) {
        const int rb = rowBase + wm * 32 + mi * 16 + (lane >> 2);
        #pragma unroll
        for (int half = 0; half < 2; half++) {
            const size_t r = (size_t)(rb + half * 8);
            #pragma unroll
            for (int nj = 0; nj < 8; nj++) {
                const int col = colBase + wn * 64 + nj * 8 + (lane & 3) * 2;
                float v0 = (acc[mi][nj][half * 2 + 0] + bias[col]) * outScale;
                float v1 = (acc[mi][nj][half * 2 + 1] + bias[col + 1]) * outScale;
                if (outF) {
                    *(float2*)&outF[r * En + col] = make_float2(v0, v1);
                } else {
                    __nv_bfloat16 h0 = __float2bfloat16(v0);
                    __nv_bfloat16 h1 = __float2bfloat16(v1);
                    *(uint32_t*)&outH[r * En + col] = pack2h(h0, h1);
                    *(uint32_t*)&outL[r * En + col] =
                        packbf(v0 - __bfloat162float(h0),
                               v1 - __bfloat162float(h1));
                }
            }
        }
    }
}

__global__ void __launch_bounds__(256, 2) gemm_qkv(
    const float* bq, const float* bk, const float* bv)
{
    const __nv_bfloat16 *Wh, *Wl; const float* bias;
    __nv_bfloat16 *oh, *ol; float sc;
    if (blockIdx.z == 0)      { Wh = g_Wqh; Wl = g_Wql; bias = bq;
                                oh = g_Qh; ol = g_Ql; sc = 0.125f; }
    else if (blockIdx.z == 1) { Wh = g_Wkh; Wl = g_Wkl; bias = bk;
                                oh = g_Kh; ol = g_Kl; sc = 1.0f; }
    else                      { Wh = g_Wvh; Wl = g_Wvl; bias = bv;
                                oh = g_Vh; ol = g_Vl; sc = 1.0f; }
    gemm_core(g_Xh, g_Xl, Wh, Wl, bias, nullptr, oh, ol, sc);
}

__global__ void __launch_bounds__(256, 2) gemm_out(const float* bo, float* out)
{
    gemm_core(g_Ah, g_Al, g_Woh, g_Wol, bo, out, nullptr, nullptr, 1.0f);
}

// =====================================================================
// Flash attention (causal) via mma.sync bf16x3. Q pre-scaled by 1/8.
// CTA: 128 q rows x 64-key tiles, 256 thr, warp w owns rows w*16..+15.
// KV tiles (Kh,Kl,Vh,Vl) [64 x 64] bf16, smem row 64+8 pad = 144B.
// =====================================================================
#define KVTILE  (64 * 144)     // 9216
#define KVSTAGE (4 * KVTILE)   // 36864
#define FL_SMEM (2 * KVSTAGE)  // 73728

__device__ __forceinline__ void kv_prefetch(
    uint32_t sb, int buf, int kt2,
    const __nv_bfloat16* Kh, const __nv_bfloat16* Kl,
    const __nv_bfloat16* Vh, const __nv_bfloat16* Vl, int tid)
{
    const uint32_t s0 = sb + buf * KVSTAGE;
    const size_t rowoff = (size_t)kt2 * 64;
    #pragma unroll
    for (int t = 0; t < 4; t++) {
        const __nv_bfloat16* src = (t == 0) ? Kh : (t == 1) ? Kl
                                 : (t == 2) ? Vh : Vl;
        #pragma unroll
        for (int i = 0; i < 2; i++) {
            int cc  = i * 256 + tid;     // 0..511
            int row = cc >> 3, seg = cc & 7;
            cp16(s0 + t * KVTILE + row * 144 + seg * 16,
                 src + (rowoff + row) * En + seg * 8);
        }
    }
}

__global__ void __launch_bounds__(256) flash_mma()
{
    extern __shared__ char smc[];
    const uint32_t sb = smem_u32(smc);
    const int tid = threadIdx.x, lane = tid & 31, wp = tid >> 5;
    const int g = lane >> 2, tg = lane & 3;
    const int qt = (int)gridDim.x - 1 - (int)blockIdx.x;   // big tiles first
    const int bh = blockIdx.y, bb = bh >> 4, hh = bh & 15;

    const size_t headoff = (size_t)bb * Tn * En + hh * HSn;
    const __nv_bfloat16* Kh = g_Kh + headoff;
    const __nv_bfloat16* Kl = g_Kl + headoff;
    const __nv_bfloat16* Vh = g_Vh + headoff;
    const __nv_bfloat16* Vl = g_Vl + headoff;

    const int nk = 2 * (qt + 1);

    kv_prefetch(sb, 0, 0, Kh, Kl, Vh, Vl, tid);
    CP_COMMIT();

    // Q fragments (hi/lo), loaded straight from gmem in frag layout
    uint32_t qh[4][4], ql[4][4];
    {
        const size_t q0 = (size_t)(bb * Tn + qt * 128 + wp * 16 + g) * En
                        + hh * HSn;
        const size_t q1 = q0 + (size_t)8 * En;
        #pragma unroll
        for (int kk = 0; kk < 4; kk++) {
            const int c0 = kk * 16 + tg * 2, c1 = c0 + 8;
            qh[kk][0] = *(const uint32_t*)&g_Qh[q0 + c0];
            qh[kk][1] = *(const uint32_t*)&g_Qh[q1 + c0];
            qh[kk][2] = *(const uint32_t*)&g_Qh[q0 + c1];
            qh[kk][3] = *(const uint32_t*)&g_Qh[q1 + c1];
            ql[kk][0] = *(const uint32_t*)&g_Ql[q0 + c0];
            ql[kk][1] = *(const uint32_t*)&g_Ql[q1 + c0];
            ql[kk][2] = *(const uint32_t*)&g_Ql[q0 + c1];
            ql[kk][3] = *(const uint32_t*)&g_Ql[q1 + c1];
        }
    }

    float o[8][4];
    #pragma unroll
    for (int i = 0; i < 8; i++)
        #pragma unroll
        for (int e = 0; e < 4; e++) o[i][e] = 0.f;
    float m0 = -1e30f, m1 = -1e30f, l0 = 0.f, l1 = 0.f;
    const int qrow0 = qt * 128 + wp * 16 + g, qrow1 = qrow0 + 8;

    const uint32_t kboff = (((lane & 16) >> 1) + (lane & 7)) * 144
                         + ((lane & 8) ? 16 : 0);

    for (int kt = 0; kt < nk; kt++) {
        if (kt + 1 < nk) {
            kv_prefetch(sb, (kt + 1) & 1, kt + 1, Kh, Kl, Vh, Vl, tid);
            CP_COMMIT();
            CP_WAIT1();
        } else {
            CP_WAIT0();
        }
        __syncthreads();
        const uint32_t s0  = sb + (kt & 1) * KVSTAGE;
        const uint32_t kmh = s0, kml = s0 + KVTILE;
        const uint32_t vmh = s0 + 2 * KVTILE, vml = s0 + 3 * KVTILE;

        // ---- S = Q K^T (bf16x3; Q pre-scaled), 8 n8-tiles of 64 keys
        float s[8][4];
        #pragma unroll
        for (int i = 0; i < 8; i++)
            #pragma unroll
            for (int e = 0; e < 4; e++) s[i][e] = 0.f;

        #pragma unroll
        for (int kk = 0; kk < 4; kk++) {
            uint32_t kbh[4][4], kbl[4][4];
            #pragma unroll
            for (int n4 = 0; n4 < 4; n4++) {
                const uint32_t r = n4 * 16 * 144 + kboff + kk * 32;
                ldsm_x4(kbh[n4], kmh + r);
                ldsm_x4(kbl[n4], kml + r);
            }
            #pragma unroll
            for (int nj = 0; nj < 8; nj++)
                mma_bf16(s[nj], qh[kk], &kbh[nj >> 1][(nj & 1) * 2]);
            #pragma unroll
            for (int nj = 0; nj < 8; nj++)
                mma_bf16(s[nj], qh[kk], &kbl[nj >> 1][(nj & 1) * 2]);
            #pragma unroll
            for (int nj = 0; nj < 8; nj++)
                mma_bf16(s[nj], ql[kk], &kbh[nj >> 1][(nj & 1) * 2]);
        }

        // ---- causal mask (diagonal tiles only; no scaling needed)
        if (kt * 64 + 63 > qrow0) {
            #pragma unroll
            for (int nj = 0; nj < 8; nj++)
                #pragma unroll
                for (int e = 0; e < 4; e++) {
                    const int key = kt * 64 + nj * 8 + tg * 2 + (e & 1);
                    const int qr  = (e < 2) ? qrow0 : qrow1;
                    if (key > qr) s[nj][e] = -1e30f;
                }
        }

        // ---- online softmax (rows g and g+8)
        float mx0 = -1e30f, mx1 = -1e30f;
        #pragma unroll
        for (int nj = 0; nj < 8; nj++) {
            mx0 = fmaxf(mx0, fmaxf(s[nj][0], s[nj][1]));
            mx1 = fmaxf(mx1, fmaxf(s[nj][2], s[nj][3]));
        }
        mx0 = fmaxf(mx0, __shfl_xor_sync(0xffffffffu, mx0, 1));
        mx0 = fmaxf(mx0, __shfl_xor_sync(0xffffffffu, mx0, 2));
        mx1 = fmaxf(mx1, __shfl_xor_sync(0xffffffffu, mx1, 1));
        mx1 = fmaxf(mx1, __shfl_xor_sync(0xffffffffu, mx1, 2));
        const float mn0 = fmaxf(m0, mx0), mn1 = fmaxf(m1, mx1);
        const float a0 = __expf(m0 - mn0), a1 = __expf(m1 - mn1);
        m0 = mn0; m1 = mn1;
        float su0 = 0.f, su1 = 0.f;
        #pragma unroll
        for (int nj = 0; nj < 8; nj++) {
            s[nj][0] = __expf(s[nj][0] - mn0); su0 += s[nj][0];
            s[nj][1] = __expf(s[nj][1] - mn0); su0 += s[nj][1];
            s[nj][2] = __expf(s[nj][2] - mn1); su1 += s[nj][2];
            s[nj][3] = __expf(s[nj][3] - mn1); su1 += s[nj][3];
        }
        su0 += __shfl_xor_sync(0xffffffffu, su0, 1);
        su0 += __shfl_xor_sync(0xffffffffu, su0, 2);
        su1 += __shfl_xor_sync(0xffffffffu, su1, 1);
        su1 += __shfl_xor_sync(0xffffffffu, su1, 2);
        l0 = l0 * a0 + su0; l1 = l1 * a1 + su1;
        #pragma unroll
        for (int nj = 0; nj < 8; nj++) {
            o[nj][0] *= a0; o[nj][1] *= a0; o[nj][2] *= a1; o[nj][3] *= a1;
        }

        // ---- O += P V (P split hi/lo built per k16 of keys)
        #pragma unroll
        for (int kk = 0; kk < 4; kk++) {
            uint32_t pah[4], pal[4];
            {
                const float* p0 = s[2 * kk];
                const float* p1 = s[2 * kk + 1];
                __nv_bfloat16 h;
                float r0, r1;
                h = __float2bfloat16(p0[0]); r0 = p0[0] - __bfloat162float(h);
                float e0 = __bfloat162float(h);
                h = __float2bfloat16(p0[1]); r1 = p0[1] - __bfloat162float(h);
                pah[0] = packbf(e0, __bfloat162float(h));
                pal[0] = packbf(r0, r1);
                h = __float2bfloat16(p0[2]); r0 = p0[2] - __bfloat162float(h);
                e0 = __bfloat162float(h);
                h = __float2bfloat16(p0[3]); r1 = p0[3] - __bfloat162float(h);
                pah[1] = packbf(e0, __bfloat162float(h));
                pal[1] = packbf(r0, r1);
                h = __float2bfloat16(p1[0]); r0 = p1[0] - __bfloat162float(h);
                e0 = __bfloat162float(h);
                h = __float2bfloat16(p1[1]); r1 = p1[1] - __bfloat162float(h);
                pah[2] = packbf(e0, __bfloat162float(h));
                pal[2] = packbf(r0, r1);
                h = __float2bfloat16(p1[2]); r0 = p1[2] - __bfloat162float(h);
                e0 = __bfloat162float(h);
                h = __float2bfloat16(p1[3]); r1 = p1[3] - __bfloat162float(h);
                pah[3] = packbf(e0, __bfloat162float(h));
                pal[3] = packbf(r0, r1);
            }
            uint32_t vbh[4][4], vbl[4][4];
            const uint32_t voff = (kk * 16 + (lane & 15)) * 144
                                + ((lane & 16) ? 16 : 0);
            #pragma unroll
            for (int nb = 0; nb < 4; nb++) {
                ldsm_x4_t(vbh[nb], vmh + voff + nb * 32);
                ldsm_x4_t(vbl[nb], vml + voff + nb * 32);
            }
            #pragma unroll
            for (int nd = 0; nd < 8; nd++)
                mma_bf16(o[nd], pah, &vbh[nd >> 1][(nd & 1) * 2]);
            #pragma unroll
            for (int nd = 0; nd < 8; nd++)
                mma_bf16(o[nd], pah, &vbl[nd >> 1][(nd & 1) * 2]);
            #pragma unroll
            for (int nd = 0; nd < 8; nd++)
                mma_bf16(o[nd], pal, &vbh[nd >> 1][(nd & 1) * 2]);
        }
        __syncthreads();   // all reads of this KV buffer done before reuse
    }

    // ---- epilogue: normalize, bf16 hi/lo split into g_Ah / g_Al
    const float i0 = 1.f / l0, i1 = 1.f / l1;
    const size_t r0 = (size_t)(bb * Tn + qrow0) * En + hh * HSn;
    const size_t r1 = r0 + (size_t)8 * En;
    #pragma unroll
    for (int nd = 0; nd < 8; nd++) {
        const int col = nd * 8 + tg * 2;
        float v0 = o[nd][0] * i0, v1 = o[nd][1] * i0;
        float v2 = o[nd][2] * i1, v3 = o[nd][3] * i1;
        __nv_bfloat16 h0 = __float2bfloat16(v0), h1 = __float2bfloat16(v1);
        __nv_bfloat16 h2 = __float2bfloat16(v2), h3 = __float2bfloat16(v3);
        *(uint32_t*)&g_Ah[r0 + col] = pack2h(h0, h1);
        *(uint32_t*)&g_Al[r0 + col] =
            packbf(v0 - __bfloat162float(h0), v1 - __bfloat162float(h1));
        *(uint32_t*)&g_Ah[r1 + col] = pack2h(h2, h3);
        *(uint32_t*)&g_Al[r1 + col] =
            packbf(v2 - __bfloat162float(h2), v3 - __bfloat162float(h3));
    }
}

// =====================================================================
extern "C" void kernel_launch(void* const* d_in, const int* in_sizes, int n_in,
                              void* d_out, int out_size)
{
    (void)in_sizes; (void)n_in; (void)out_size;
    const float* X  = (const float*)d_in[0];
    const float* Wq = (const float*)d_in[1];
    const float* bq = (const float*)d_in[2];
    const float* Wk = (const float*)d_in[3];
    const float* bk = (const float*)d_in[4];
    const float* Wv = (const float*)d_in[5];
    const float* bv = (const float*)d_in[6];
    const float* Wo = (const float*)d_in[7];
    const float* bo = (const float*)d_in[8];
    float* out = (float*)d_out;

    cudaFuncSetAttribute(gemm_qkv,
                         cudaFuncAttributeMaxDynamicSharedMemorySize, GEMM_SMEM);
    cudaFuncSetAttribute(gemm_out,
                         cudaFuncAttributeMaxDynamicSharedMemorySize, GEMM_SMEM);
    cudaFuncSetAttribute(flash_mma,
                         cudaFuncAttributeMaxDynamicSharedMemorySize, FL_SMEM);

    dim3 blk(256);
    split_all<<<8192, 256>>>(X, Wq, Wk, Wv, Wo);
    gemm_qkv<<<dim3(En / 128, Mn / 128, 3), blk, GEMM_SMEM>>>(bq, bk, bv);
    flash_mma<<<dim3(Tn / 128, Bn * NHn), blk, FL_SMEM>>>();
    gemm_out<<<dim3(En / 128, Mn / 128), blk, GEMM_SMEM>>>(bo, out);
}

// round 6
// speedup vs baseline: 1.3818x; 1.3818x over previous
#include <cuda_runtime.h>
#include <cuda_fp16.h>
#include <cstdint>

// Problem constants
#define Bn  2
#define Tn  2048
#define En  1024
#define NHn 16
#define HSn 64
#define Mn  (Bn * Tn)        // 4096 token rows

// ---------------- scratch (device globals; no allocation) ----------------
// fp16x2 scheme: "A" operands stored fp16-only (X, Q, attnOut); "B" operands
// stored as fp16 hi/lo pairs (all weights, K, V).
__device__ __half g_Xh[(size_t)Mn * En];
__device__ __half g_Wqh[(size_t)En * En];
__device__ __half g_Wql[(size_t)En * En];
__device__ __half g_Wkh[(size_t)En * En];
__device__ __half g_Wkl[(size_t)En * En];
__device__ __half g_Wvh[(size_t)En * En];
__device__ __half g_Wvl[(size_t)En * En];
__device__ __half g_Woh[(size_t)En * En];
__device__ __half g_Wol[(size_t)En * En];
__device__ __half g_Qh[(size_t)Mn * En];   // pre-scaled by 1/8
__device__ __half g_Kh[(size_t)Mn * En];
__device__ __half g_Kl[(size_t)Mn * En];
__device__ __half g_Vh[(size_t)Mn * En];
__device__ __half g_Vl[(size_t)Mn * En];
__device__ __half g_Ah[(size_t)Mn * En];

// =====================================================================
// Baseline-PTX helpers
// =====================================================================
__device__ __forceinline__ uint32_t smem_u32(const void* p) {
    uint32_t a;
    asm("{ .reg .u64 t; cvta.to.shared.u64 t, %1; cvt.u32.u64 %0, t; }"
        : "=r"(a) : "l"(p));
    return a;
}

__device__ __forceinline__ void mma_f16(float* d, const uint32_t* a,
                                        const uint32_t* b) {
    asm volatile(
        "mma.sync.aligned.m16n8k16.row.col.f32.f16.f16.f32 "
        "{%0,%1,%2,%3}, {%4,%5,%6,%7}, {%8,%9}, {%0,%1,%2,%3};\n"
        : "+f"(d[0]), "+f"(d[1]), "+f"(d[2]), "+f"(d[3])
        : "r"(a[0]), "r"(a[1]), "r"(a[2]), "r"(a[3]), "r"(b[0]), "r"(b[1]));
}

__device__ __forceinline__ void ldsm_x4(uint32_t* r, uint32_t a) {
    asm volatile("ldmatrix.sync.aligned.m8n8.x4.shared.b16 {%0,%1,%2,%3}, [%4];"
                 : "=r"(r[0]), "=r"(r[1]), "=r"(r[2]), "=r"(r[3]) : "r"(a));
}
__device__ __forceinline__ void ldsm_x4_t(uint32_t* r, uint32_t a) {
    asm volatile("ldmatrix.sync.aligned.m8n8.x4.trans.shared.b16 {%0,%1,%2,%3}, [%4];"
                 : "=r"(r[0]), "=r"(r[1]), "=r"(r[2]), "=r"(r[3]) : "r"(a));
}

__device__ __forceinline__ void cp16(uint32_t d, const void* g) {
    asm volatile("cp.async.cg.shared.global [%0], [%1], 16;" :: "r"(d), "l"(g));
}
#define CP_COMMIT() asm volatile("cp.async.commit_group;" ::: "memory")
#define CP_WAIT0()  asm volatile("cp.async.wait_group 0;" ::: "memory")
#define CP_WAIT1()  asm volatile("cp.async.wait_group 1;" ::: "memory")

__device__ __forceinline__ uint32_t packh(__half a, __half b) {
    __half2 t(a, b);
    return *reinterpret_cast<uint32_t*>(&t);
}

// =====================================================================
// Fused split kernel: X -> fp16; weights -> fp16 hi/lo pairs.
// =====================================================================
__global__ void __launch_bounds__(256) split_all(
    const float* __restrict__ X,  const float* __restrict__ Wq,
    const float* __restrict__ Wk, const float* __restrict__ Wv,
    const float* __restrict__ Wo)
{
    const int i = blockIdx.x * blockDim.x + threadIdx.x;   // float4 index
    if (i < (1 << 20)) {   // X: fp16 only
        const float4 v = *(const float4*)(X + (size_t)i * 4);
        uint2 hh;
        hh.x = packh(__float2half(v.x), __float2half(v.y));
        hh.y = packh(__float2half(v.z), __float2half(v.w));
        *(uint2*)(g_Xh + (size_t)i * 4) = hh;
        return;
    }
    const int r = i - (1 << 20);
    const int seg = r >> 18;
    const int base = r & ((1 << 18) - 1);
    const float* src; __half *hi, *lo;
    switch (seg) {
        case 0:  src = Wq; hi = g_Wqh; lo = g_Wql; break;
        case 1:  src = Wk; hi = g_Wkh; lo = g_Wkl; break;
        case 2:  src = Wv; hi = g_Wvh; lo = g_Wvl; break;
        default: src = Wo; hi = g_Woh; lo = g_Wol; break;
    }
    const float4 v = *(const float4*)(src + (size_t)base * 4);
    const __half h0 = __float2half(v.x), h1 = __float2half(v.y);
    const __half h2 = __float2half(v.z), h3 = __float2half(v.w);
    uint2 hh, ll;
    hh.x = packh(h0, h1);
    hh.y = packh(h2, h3);
    ll.x = packh(__float2half(v.x - __half2float(h0)),
                 __float2half(v.y - __half2float(h1)));
    ll.y = packh(__float2half(v.z - __half2float(h2)),
                 __float2half(v.w - __half2float(h3)));
    *(uint2*)(hi + (size_t)base * 4) = hh;
    *(uint2*)(lo + (size_t)base * 4) = ll;
}

// =====================================================================
// GEMM: C[128x128] = A * (Bh+Bl)^T + bias, fp16x2 via mma.sync.
// 256 thr, 8 warps (4m x 2n), k-stage 32, cp.async double buffer.
// 3 smem tiles per stage (Ah, Bh, Bl), 2 MMA passes.
// =====================================================================
#define GTILE  (128 * 80)      // one [128 x 32] fp16 tile (padded rows)
#define GSTAGE (3 * GTILE)     // Ah, Bh, Bl
#define GEMM_SMEM (2 * GSTAGE) // 61440

__device__ __forceinline__ void gemm_prefetch(
    uint32_t sbs, const __half* pA0,
    const __half* pB0, const __half* pB1, int k0, int tid)
{
    #pragma unroll
    for (int t = 0; t < 3; t++) {
        const __half* s = (t == 0) ? pA0 : (t == 1) ? pB0 : pB1;
        #pragma unroll
        for (int i = 0; i < 2; i++) {
            int cc  = i * 256 + tid;       // 0..511
            int row = cc >> 2, seg = cc & 3;
            cp16(sbs + t * GTILE + row * 80 + seg * 16,
                 s + (size_t)row * En + k0 + seg * 8);
        }
    }
}

__device__ __forceinline__ void gemm_core(
    const __half* __restrict__ Ah,
    const __half* __restrict__ Bh, const __half* __restrict__ Bl,
    const float* __restrict__ bias, float* __restrict__ outF,
    __half* __restrict__ outH, __half* __restrict__ outL,
    float outScale)
{
    extern __shared__ char smc[];
    const uint32_t sb = smem_u32(smc);
    const int tid = threadIdx.x, lane = tid & 31, wid = tid >> 5;
    const int wm = wid & 3, wn = wid >> 2;
    const int rowBase = blockIdx.y * 128, colBase = blockIdx.x * 128;

    const __half* pA0 = Ah + (size_t)rowBase * En;
    const __half* pB0 = Bh + (size_t)colBase * En;
    const __half* pB1 = Bl + (size_t)colBase * En;

    float acc[2][8][4];
    #pragma unroll
    for (int i = 0; i < 2; i++)
        #pragma unroll
        for (int j = 0; j < 8; j++)
            #pragma unroll
            for (int e = 0; e < 4; e++) acc[i][j][e] = 0.f;

    gemm_prefetch(sb, pA0, pB0, pB1, 0, tid);
    CP_COMMIT();

    const uint32_t aoff = (lane & 15) * 80 + (lane >> 4) * 16;
    const uint32_t boff = (((lane & 16) >> 1) + (lane & 7)) * 80
                        + ((lane & 8) ? 16 : 0);

    for (int st = 0; st < En / 32; st++) {
        if (st + 1 < En / 32) {
            gemm_prefetch(sb + ((st + 1) & 1) * GSTAGE,
                          pA0, pB0, pB1, (st + 1) * 32, tid);
            CP_COMMIT();
            CP_WAIT1();
        } else {
            CP_WAIT0();
        }
        __syncthreads();
        const uint32_t s0 = sb + (st & 1) * GSTAGE;
        const uint32_t aH = s0, bH = s0 + GTILE, bL = s0 + 2 * GTILE;

        #pragma unroll
        for (int kk = 0; kk < 2; kk++) {
            uint32_t ah[2][4], bh4[4][4], bl4[4][4];
            #pragma unroll
            for (int mi = 0; mi < 2; mi++)
                ldsm_x4(ah[mi], aH + (wm * 32 + mi * 16) * 80 + aoff + kk * 32);
            #pragma unroll
            for (int n4 = 0; n4 < 4; n4++) {
                const uint32_t r = (wn * 64 + n4 * 16) * 80 + boff + kk * 32;
                ldsm_x4(bh4[n4], bH + r);
                ldsm_x4(bl4[n4], bL + r);
            }
            // 2 passes: C = Ah*Bh + Ah*Bl
            #pragma unroll
            for (int mi = 0; mi < 2; mi++)
                #pragma unroll
                for (int nj = 0; nj < 8; nj++)
                    mma_f16(acc[mi][nj], ah[mi], &bh4[nj >> 1][(nj & 1) * 2]);
            #pragma unroll
            for (int mi = 0; mi < 2; mi++)
                #pragma unroll
                for (int nj = 0; nj < 8; nj++)
                    mma_f16(acc[mi][nj], ah[mi], &bl4[nj >> 1][(nj & 1) * 2]);
        }
        __syncthreads();
    }

    // epilogue
    #pragma unroll
    for (int mi = 0; mi < 2; mi++) {
        const int rb = rowBase + wm * 32 + mi * 16 + (lane >> 2);
        #pragma unroll
        for (int half = 0; half < 2; half++) {
            const size_t r = (size_t)(rb + half * 8);
            #pragma unroll
            for (int nj = 0; nj < 8; nj++) {
                const int col = colBase + wn * 64 + nj * 8 + (lane & 3) * 2;
                float v0 = (acc[mi][nj][half * 2 + 0] + bias[col]) * outScale;
                float v1 = (acc[mi][nj][half * 2 + 1] + bias[col + 1]) * outScale;
                if (outF) {
                    *(float2*)&outF[r * En + col] = make_float2(v0, v1);
                } else if (outL) {       // fp16 hi/lo pair (K, V)
                    __half h0 = __float2half(v0), h1 = __float2half(v1);
                    *(uint32_t*)&outH[r * En + col] = packh(h0, h1);
                    *(uint32_t*)&outL[r * En + col] =
                        packh(__float2half(v0 - __half2float(h0)),
                              __float2half(v1 - __half2float(h1)));
                } else {                 // fp16 only (Q, attn out)
                    *(uint32_t*)&outH[r * En + col] =
                        packh(__float2half(v0), __float2half(v1));
                }
            }
        }
    }
}

__global__ void __launch_bounds__(256, 2) gemm_qkv(
    const float* bq, const float* bk, const float* bv)
{
    if (blockIdx.z == 0)
        gemm_core(g_Xh, g_Wqh, g_Wql, bq, nullptr, g_Qh, nullptr, 0.125f);
    else if (blockIdx.z == 1)
        gemm_core(g_Xh, g_Wkh, g_Wkl, bk, nullptr, g_Kh, g_Kl, 1.0f);
    else
        gemm_core(g_Xh, g_Wvh, g_Wvl, bv, nullptr, g_Vh, g_Vl, 1.0f);
}

__global__ void __launch_bounds__(256, 2) gemm_out(const float* bo, float* out)
{
    gemm_core(g_Ah, g_Woh, g_Wol, bo, out, nullptr, nullptr, 1.0f);
}

// =====================================================================
// Flash attention (causal) via mma.sync fp16x2. Q pre-scaled by 1/8.
// CTA: 128 q rows x 64-key tiles, 256 thr, warp w owns rows w*16..+15.
// KV tiles (Kh,Kl,Vh,Vl) [64 x 64] fp16, smem row 64+8 pad = 144B.
// S = Qh*(Kh+Kl);  O = Ph*(Vh+Vl)  (2 MMA passes each).
// =====================================================================
#define KVTILE  (64 * 144)     // 9216
#define KVSTAGE (4 * KVTILE)   // 36864
#define FL_SMEM (2 * KVSTAGE)  // 73728

__device__ __forceinline__ void kv_prefetch(
    uint32_t sb, int buf, int kt2,
    const __half* Kh, const __half* Kl,
    const __half* Vh, const __half* Vl, int tid)
{
    const uint32_t s0 = sb + buf * KVSTAGE;
    const size_t rowoff = (size_t)kt2 * 64;
    #pragma unroll
    for (int t = 0; t < 4; t++) {
        const __half* src = (t == 0) ? Kh : (t == 1) ? Kl
                          : (t == 2) ? Vh : Vl;
        #pragma unroll
        for (int i = 0; i < 2; i++) {
            int cc  = i * 256 + tid;     // 0..511
            int row = cc >> 3, seg = cc & 7;
            cp16(s0 + t * KVTILE + row * 144 + seg * 16,
                 src + (rowoff + row) * En + seg * 8);
        }
    }
}

__global__ void __launch_bounds__(256) flash_mma()
{
    extern __shared__ char smc[];
    const uint32_t sb = smem_u32(smc);
    const int tid = threadIdx.x, lane = tid & 31, wp = tid >> 5;
    const int g = lane >> 2, tg = lane & 3;
    const int qt = (int)gridDim.x - 1 - (int)blockIdx.x;   // big tiles first
    const int bh = blockIdx.y, bb = bh >> 4, hh = bh & 15;

    const size_t headoff = (size_t)bb * Tn * En + hh * HSn;
    const __half* Kh = g_Kh + headoff;
    const __half* Kl = g_Kl + headoff;
    const __half* Vh = g_Vh + headoff;
    const __half* Vl = g_Vl + headoff;

    const int nk = 2 * (qt + 1);

    kv_prefetch(sb, 0, 0, Kh, Kl, Vh, Vl, tid);
    CP_COMMIT();

    // Q fragments (fp16 hi only), loaded straight from gmem in frag layout
    uint32_t qh[4][4];
    {
        const size_t q0 = (size_t)(bb * Tn + qt * 128 + wp * 16 + g) * En
                        + hh * HSn;
        const size_t q1 = q0 + (size_t)8 * En;
        #pragma unroll
        for (int kk = 0; kk < 4; kk++) {
            const int c0 = kk * 16 + tg * 2, c1 = c0 + 8;
            qh[kk][0] = *(const uint32_t*)&g_Qh[q0 + c0];
            qh[kk][1] = *(const uint32_t*)&g_Qh[q1 + c0];
            qh[kk][2] = *(const uint32_t*)&g_Qh[q0 + c1];
            qh[kk][3] = *(const uint32_t*)&g_Qh[q1 + c1];
        }
    }

    float o[8][4];
    #pragma unroll
    for (int i = 0; i < 8; i++)
        #pragma unroll
        for (int e = 0; e < 4; e++) o[i][e] = 0.f;
    float m0 = -1e30f, m1 = -1e30f, l0 = 0.f, l1 = 0.f;
    const int qrow0 = qt * 128 + wp * 16 + g, qrow1 = qrow0 + 8;

    const uint32_t kboff = (((lane & 16) >> 1) + (lane & 7)) * 144
                         + ((lane & 8) ? 16 : 0);

    for (int kt = 0; kt < nk; kt++) {
        if (kt + 1 < nk) {
            kv_prefetch(sb, (kt + 1) & 1, kt + 1, Kh, Kl, Vh, Vl, tid);
            CP_COMMIT();
            CP_WAIT1();
        } else {
            CP_WAIT0();
        }
        __syncthreads();
        const uint32_t s0  = sb + (kt & 1) * KVSTAGE;
        const uint32_t kmh = s0, kml = s0 + KVTILE;
        const uint32_t vmh = s0 + 2 * KVTILE, vml = s0 + 3 * KVTILE;

        // ---- S = Qh (Kh+Kl)^T, 8 n8-tiles of 64 keys
        float s[8][4];
        #pragma unroll
        for (int i = 0; i < 8; i++)
            #pragma unroll
            for (int e = 0; e < 4; e++) s[i][e] = 0.f;

        #pragma unroll
        for (int kk = 0; kk < 4; kk++) {
            uint32_t kbh[4][4], kbl[4][4];
            #pragma unroll
            for (int n4 = 0; n4 < 4; n4++) {
                const uint32_t r = n4 * 16 * 144 + kboff + kk * 32;
                ldsm_x4(kbh[n4], kmh + r);
                ldsm_x4(kbl[n4], kml + r);
            }
            #pragma unroll
            for (int nj = 0; nj < 8; nj++)
                mma_f16(s[nj], qh[kk], &kbh[nj >> 1][(nj & 1) * 2]);
            #pragma unroll
            for (int nj = 0; nj < 8; nj++)
                mma_f16(s[nj], qh[kk], &kbl[nj >> 1][(nj & 1) * 2]);
        }

        // ---- causal mask (diagonal tiles only)
        if (kt * 64 + 63 > qrow0) {
            #pragma unroll
            for (int nj = 0; nj < 8; nj++)
                #pragma unroll
                for (int e = 0; e < 4; e++) {
                    const int key = kt * 64 + nj * 8 + tg * 2 + (e & 1);
                    const int qr  = (e < 2) ? qrow0 : qrow1;
                    if (key > qr) s[nj][e] = -1e30f;
                }
        }

        // ---- online softmax (rows g and g+8)
        float mx0 = -1e30f, mx1 = -1e30f;
        #pragma unroll
        for (int nj = 0; nj < 8; nj++) {
            mx0 = fmaxf(mx0, fmaxf(s[nj][0], s[nj][1]));
            mx1 = fmaxf(mx1, fmaxf(s[nj][2], s[nj][3]));
        }
        mx0 = fmaxf(mx0, __shfl_xor_sync(0xffffffffu, mx0, 1));
        mx0 = fmaxf(mx0, __shfl_xor_sync(0xffffffffu, mx0, 2));
        mx1 = fmaxf(mx1, __shfl_xor_sync(0xffffffffu, mx1, 1));
        mx1 = fmaxf(mx1, __shfl_xor_sync(0xffffffffu, mx1, 2));
        const float mn0 = fmaxf(m0, mx0), mn1 = fmaxf(m1, mx1);
        const float a0 = __expf(m0 - mn0), a1 = __expf(m1 - mn1);
        m0 = mn0; m1 = mn1;
        float su0 = 0.f, su1 = 0.f;
        #pragma unroll
        for (int nj = 0; nj < 8; nj++) {
            s[nj][0] = __expf(s[nj][0] - mn0); su0 += s[nj][0];
            s[nj][1] = __expf(s[nj][1] - mn0); su0 += s[nj][1];
            s[nj][2] = __expf(s[nj][2] - mn1); su1 += s[nj][2];
            s[nj][3] = __expf(s[nj][3] - mn1); su1 += s[nj][3];
        }
        su0 += __shfl_xor_sync(0xffffffffu, su0, 1);
        su0 += __shfl_xor_sync(0xffffffffu, su0, 2);
        su1 += __shfl_xor_sync(0xffffffffu, su1, 1);
        su1 += __shfl_xor_sync(0xffffffffu, su1, 2);
        l0 = l0 * a0 + su0; l1 = l1 * a1 + su1;
        #pragma unroll
        for (int nj = 0; nj < 8; nj++) {
            o[nj][0] *= a0; o[nj][1] *= a0; o[nj][2] *= a1; o[nj][3] *= a1;
        }

        // ---- O += Ph (Vh+Vl)
        #pragma unroll
        for (int kk = 0; kk < 4; kk++) {
            uint32_t pah[4];
            {
                const float* p0 = s[2 * kk];
                const float* p1 = s[2 * kk + 1];
                pah[0] = packh(__float2half(p0[0]), __float2half(p0[1]));
                pah[1] = packh(__float2half(p0[2]), __float2half(p0[3]));
                pah[2] = packh(__float2half(p1[0]), __float2half(p1[1]));
                pah[3] = packh(__float2half(p1[2]), __float2half(p1[3]));
            }
            uint32_t vbh[4][4], vbl[4][4];
            const uint32_t voff = (kk * 16 + (lane & 15)) * 144
                                + ((lane & 16) ? 16 : 0);
            #pragma unroll
            for (int nb = 0; nb < 4; nb++) {
                ldsm_x4_t(vbh[nb], vmh + voff + nb * 32);
                ldsm_x4_t(vbl[nb], vml + voff + nb * 32);
            }
            #pragma unroll
            for (int nd = 0; nd < 8; nd++)
                mma_f16(o[nd], pah, &vbh[nd >> 1][(nd & 1) * 2]);
            #pragma unroll
            for (int nd = 0; nd < 8; nd++)
                mma_f16(o[nd], pah, &vbl[nd >> 1][(nd & 1) * 2]);
        }
        __syncthreads();   // all reads of this KV buffer done before reuse
    }

    // ---- epilogue: normalize, fp16 store into g_Ah
    const float i0 = 1.f / l0, i1 = 1.f / l1;
    const size_t r0 = (size_t)(bb * Tn + qrow0) * En + hh * HSn;
    const size_t r1 = r0 + (size_t)8 * En;
    #pragma unroll
    for (int nd = 0; nd < 8; nd++) {
        const int col = nd * 8 + tg * 2;
        *(uint32_t*)&g_Ah[r0 + col] =
            packh(__float2half(o[nd][0] * i0), __float2half(o[nd][1] * i0));
        *(uint32_t*)&g_Ah[r1 + col] =
            packh(__float2half(o[nd][2] * i1), __float2half(o[nd][3] * i1));
    }
}

// =====================================================================
extern "C" void kernel_launch(void* const* d_in, const int* in_sizes, int n_in,
                              void* d_out, int out_size)
{
    (void)in_sizes; (void)n_in; (void)out_size;
    const float* X  = (const float*)d_in[0];
    const float* Wq = (const float*)d_in[1];
    const float* bq = (const float*)d_in[2];
    const float* Wk = (const float*)d_in[3];
    const float* bk = (const float*)d_in[4];
    const float* Wv = (const float*)d_in[5];
    const float* bv = (const float*)d_in[6];
    const float* Wo = (const float*)d_in[7];
    const float* bo = (const float*)d_in[8];
    float* out = (float*)d_out;

    cudaFuncSetAttribute(gemm_qkv,
                         cudaFuncAttributeMaxDynamicSharedMemorySize, GEMM_SMEM);
    cudaFuncSetAttribute(gemm_out,
                         cudaFuncAttributeMaxDynamicSharedMemorySize, GEMM_SMEM);
    cudaFuncSetAttribute(flash_mma,
                         cudaFuncAttributeMaxDynamicSharedMemorySize, FL_SMEM);

    dim3 blk(256);
    split_all<<<8192, 256>>>(X, Wq, Wk, Wv, Wo);
    gemm_qkv<<<dim3(En / 128, Mn / 128, 3), blk, GEMM_SMEM>>>(bq, bk, bv);
    flash_mma<<<dim3(Tn / 128, Bn * NHn), blk, FL_SMEM>>>();
    gemm_out<<<dim3(En / 128, Mn / 128), blk, GEMM_SMEM>>>(bo, out);
}

// round 7
// speedup vs baseline: 1.5373x; 1.1125x over previous
#include <cuda_runtime.h>
#include <cuda_fp16.h>
#include <cstdint>

// Problem constants
#define Bn  2
#define Tn  2048
#define En  1024
#define NHn 16
#define HSn 64
#define Mn  (Bn * Tn)        // 4096 token rows

// ---------------- scratch (device globals; no allocation) ----------------
// fp16x2 scheme: "A" operands fp16-only (X, Q, attnOut, V); "B" operands
// fp16 hi/lo pairs (all weights, K).
__device__ __half g_Xh[(size_t)Mn * En];
__device__ __half g_Wqh[(size_t)En * En];
__device__ __half g_Wql[(size_t)En * En];
__device__ __half g_Wkh[(size_t)En * En];
__device__ __half g_Wkl[(size_t)En * En];
__device__ __half g_Wvh[(size_t)En * En];
__device__ __half g_Wvl[(size_t)En * En];
__device__ __half g_Woh[(size_t)En * En];
__device__ __half g_Wol[(size_t)En * En];
__device__ __half g_Qh[(size_t)Mn * En];   // pre-scaled by 1/8
__device__ __half g_Kh[(size_t)Mn * En];
__device__ __half g_Kl[(size_t)Mn * En];
__device__ __half g_Vh[(size_t)Mn * En];   // fp16 only
__device__ __half g_Ah[(size_t)Mn * En];

// =====================================================================
// Baseline-PTX helpers
// =====================================================================
__device__ __forceinline__ uint32_t smem_u32(const void* p) {
    uint32_t a;
    asm("{ .reg .u64 t; cvta.to.shared.u64 t, %1; cvt.u32.u64 %0, t; }"
        : "=r"(a) : "l"(p));
    return a;
}

__device__ __forceinline__ void mma_f16(float* d, const uint32_t* a,
                                        const uint32_t* b) {
    asm volatile(
        "mma.sync.aligned.m16n8k16.row.col.f32.f16.f16.f32 "
        "{%0,%1,%2,%3}, {%4,%5,%6,%7}, {%8,%9}, {%0,%1,%2,%3};\n"
        : "+f"(d[0]), "+f"(d[1]), "+f"(d[2]), "+f"(d[3])
        : "r"(a[0]), "r"(a[1]), "r"(a[2]), "r"(a[3]), "r"(b[0]), "r"(b[1]));
}

__device__ __forceinline__ void ldsm_x4(uint32_t* r, uint32_t a) {
    asm volatile("ldmatrix.sync.aligned.m8n8.x4.shared.b16 {%0,%1,%2,%3}, [%4];"
                 : "=r"(r[0]), "=r"(r[1]), "=r"(r[2]), "=r"(r[3]) : "r"(a));
}
__device__ __forceinline__ void ldsm_x4_t(uint32_t* r, uint32_t a) {
    asm volatile("ldmatrix.sync.aligned.m8n8.x4.trans.shared.b16 {%0,%1,%2,%3}, [%4];"
                 : "=r"(r[0]), "=r"(r[1]), "=r"(r[2]), "=r"(r[3]) : "r"(a));
}

__device__ __forceinline__ void cp16(uint32_t d, const void* g) {
    asm volatile("cp.async.cg.shared.global [%0], [%1], 16;" :: "r"(d), "l"(g));
}
#define CP_COMMIT() asm volatile("cp.async.commit_group;" ::: "memory")
#define CP_WAIT0()  asm volatile("cp.async.wait_group 0;" ::: "memory")
#define CP_WAIT1()  asm volatile("cp.async.wait_group 1;" ::: "memory")

__device__ __forceinline__ uint32_t packh(__half a, __half b) {
    __half2 t(a, b);
    return *reinterpret_cast<uint32_t*>(&t);
}

// =====================================================================
// Fused split kernel: X -> fp16; weights -> fp16 hi/lo pairs.
// =====================================================================
__global__ void __launch_bounds__(256) split_all(
    const float* __restrict__ X,  const float* __restrict__ Wq,
    const float* __restrict__ Wk, const float* __restrict__ Wv,
    const float* __restrict__ Wo)
{
    const int i = blockIdx.x * blockDim.x + threadIdx.x;   // float4 index
    if (i < (1 << 20)) {   // X: fp16 only
        const float4 v = *(const float4*)(X + (size_t)i * 4);
        uint2 hh;
        hh.x = packh(__float2half(v.x), __float2half(v.y));
        hh.y = packh(__float2half(v.z), __float2half(v.w));
        *(uint2*)(g_Xh + (size_t)i * 4) = hh;
        return;
    }
    const int r = i - (1 << 20);
    const int seg = r >> 18;
    const int base = r & ((1 << 18) - 1);
    const float* src; __half *hi, *lo;
    switch (seg) {
        case 0:  src = Wq; hi = g_Wqh; lo = g_Wql; break;
        case 1:  src = Wk; hi = g_Wkh; lo = g_Wkl; break;
        case 2:  src = Wv; hi = g_Wvh; lo = g_Wvl; break;
        default: src = Wo; hi = g_Woh; lo = g_Wol; break;
    }
    const float4 v = *(const float4*)(src + (size_t)base * 4);
    const __half h0 = __float2half(v.x), h1 = __float2half(v.y);
    const __half h2 = __float2half(v.z), h3 = __float2half(v.w);
    uint2 hh, ll;
    hh.x = packh(h0, h1);
    hh.y = packh(h2, h3);
    ll.x = packh(__float2half(v.x - __half2float(h0)),
                 __float2half(v.y - __half2float(h1)));
    ll.y = packh(__float2half(v.z - __half2float(h2)),
                 __float2half(v.w - __half2float(h3)));
    *(uint2*)(hi + (size_t)base * 4) = hh;
    *(uint2*)(lo + (size_t)base * 4) = ll;
}

// =====================================================================
// GEMM: C[128x128] = A * (Bh+Bl)^T + bias, fp16x2 via mma.sync.
// 256 thr, 8 warps (4m x 2n), k-stage 32, cp.async TRIPLE buffer,
// ONE __syncthreads per stage.
// =====================================================================
#define GTILE  (128 * 80)      // one [128 x 32] fp16 tile (padded rows)
#define GSTAGE (3 * GTILE)     // Ah, Bh, Bl
#define GEMM_SMEM (3 * GSTAGE) // 92160 (3-stage pipeline)
#define NSTAGES (En / 32)      // 32

__device__ __forceinline__ void gemm_prefetch(
    uint32_t sbs, const __half* pA0,
    const __half* pB0, const __half* pB1, int k0, int tid)
{
    #pragma unroll
    for (int t = 0; t < 3; t++) {
        const __half* s = (t == 0) ? pA0 : (t == 1) ? pB0 : pB1;
        #pragma unroll
        for (int i = 0; i < 2; i++) {
            int cc  = i * 256 + tid;       // 0..511
            int row = cc >> 2, seg = cc & 3;
            cp16(sbs + t * GTILE + row * 80 + seg * 16,
                 s + (size_t)row * En + k0 + seg * 8);
        }
    }
}

__device__ __forceinline__ void gemm_core(
    const __half* __restrict__ Ah,
    const __half* __restrict__ Bh, const __half* __restrict__ Bl,
    const float* __restrict__ bias, float* __restrict__ outF,
    __half* __restrict__ outH, __half* __restrict__ outL,
    float outScale)
{
    extern __shared__ char smc[];
    const uint32_t sb = smem_u32(smc);
    const int tid = threadIdx.x, lane = tid & 31, wid = tid >> 5;
    const int wm = wid & 3, wn = wid >> 2;
    const int rowBase = blockIdx.y * 128, colBase = blockIdx.x * 128;

    const __half* pA0 = Ah + (size_t)rowBase * En;
    const __half* pB0 = Bh + (size_t)colBase * En;
    const __half* pB1 = Bl + (size_t)colBase * En;

    float acc[2][8][4];
    #pragma unroll
    for (int i = 0; i < 2; i++)
        #pragma unroll
        for (int j = 0; j < 8; j++)
            #pragma unroll
            for (int e = 0; e < 4; e++) acc[i][j][e] = 0.f;

    gemm_prefetch(sb, pA0, pB0, pB1, 0, tid);
    CP_COMMIT();
    gemm_prefetch(sb + GSTAGE, pA0, pB0, pB1, 32, tid);
    CP_COMMIT();

    const uint32_t aoff = (lane & 15) * 80 + (lane >> 4) * 16;
    const uint32_t boff = (((lane & 16) >> 1) + (lane & 7)) * 80
                        + ((lane & 8) ? 16 : 0);

    uint32_t bufc = 0, bufp = 2;   // compute buf, prefetch buf (mod-3 counters)
    for (int st = 0; st < NSTAGES; st++) {
        CP_WAIT1();          // stage st landed (st+1 may still be in flight)
        __syncthreads();     // also: all readers of buf[bufp] are done
        if (st + 2 < NSTAGES) {
            gemm_prefetch(sb + bufp * GSTAGE, pA0, pB0, pB1, (st + 2) * 32, tid);
            CP_COMMIT();
        }
        const uint32_t s0 = sb + bufc * GSTAGE;
        bufc = (bufc == 2) ? 0 : bufc + 1;
        bufp = (bufp == 2) ? 0 : bufp + 1;
        const uint32_t aH = s0, bH = s0 + GTILE, bL = s0 + 2 * GTILE;

        #pragma unroll
        for (int kk = 0; kk < 2; kk++) {
            uint32_t ah[2][4], bh4[4][4], bl4[4][4];
            #pragma unroll
            for (int mi = 0; mi < 2; mi++)
                ldsm_x4(ah[mi], aH + (wm * 32 + mi * 16) * 80 + aoff + kk * 32);
            #pragma unroll
            for (int n4 = 0; n4 < 4; n4++) {
                const uint32_t r = (wn * 64 + n4 * 16) * 80 + boff + kk * 32;
                ldsm_x4(bh4[n4], bH + r);
                ldsm_x4(bl4[n4], bL + r);
            }
            #pragma unroll
            for (int mi = 0; mi < 2; mi++)
                #pragma unroll
                for (int nj = 0; nj < 8; nj++)
                    mma_f16(acc[mi][nj], ah[mi], &bh4[nj >> 1][(nj & 1) * 2]);
            #pragma unroll
            for (int mi = 0; mi < 2; mi++)
                #pragma unroll
                for (int nj = 0; nj < 8; nj++)
                    mma_f16(acc[mi][nj], ah[mi], &bl4[nj >> 1][(nj & 1) * 2]);
        }
    }

    // epilogue
    #pragma unroll
    for (int mi = 0; mi < 2; mi++) {
        const int rb = rowBase + wm * 32 + mi * 16 + (lane >> 2);
        #pragma unroll
        for (int half = 0; half < 2; half++) {
            const size_t r = (size_t)(rb + half * 8);
            #pragma unroll
            for (int nj = 0; nj < 8; nj++) {
                const int col = colBase + wn * 64 + nj * 8 + (lane & 3) * 2;
                float v0 = (acc[mi][nj][half * 2 + 0] + bias[col]) * outScale;
                float v1 = (acc[mi][nj][half * 2 + 1] + bias[col + 1]) * outScale;
                if (outF) {
                    *(float2*)&outF[r * En + col] = make_float2(v0, v1);
                } else if (outL) {       // fp16 hi/lo pair (K)
                    __half h0 = __float2half(v0), h1 = __float2half(v1);
                    *(uint32_t*)&outH[r * En + col] = packh(h0, h1);
                    *(uint32_t*)&outL[r * En + col] =
                        packh(__float2half(v0 - __half2float(h0)),
                              __float2half(v1 - __half2float(h1)));
                } else {                 // fp16 only (Q, V, attn out)
                    *(uint32_t*)&outH[r * En + col] =
                        packh(__float2half(v0), __float2half(v1));
                }
            }
        }
    }
}

__global__ void __launch_bounds__(256, 2) gemm_qkv(
    const float* bq, const float* bk, const float* bv)
{
    if (blockIdx.z == 0)
        gemm_core(g_Xh, g_Wqh, g_Wql, bq, nullptr, g_Qh, nullptr, 0.125f);
    else if (blockIdx.z == 1)
        gemm_core(g_Xh, g_Wkh, g_Wkl, bk, nullptr, g_Kh, g_Kl, 1.0f);
    else
        gemm_core(g_Xh, g_Wvh, g_Wvl, bv, nullptr, g_Vh, nullptr, 1.0f);
}

__global__ void __launch_bounds__(256, 2) gemm_out(const float* bo, float* out)
{
    gemm_core(g_Ah, g_Woh, g_Wol, bo, out, nullptr, nullptr, 1.0f);
}

// =====================================================================
// Flash attention (causal) via mma.sync. Q pre-scaled by 1/8.
// S = Qh*(Kh+Kl);  O = Ph*Vh (V fp16-only).
// KV stage: 3 tiles [64x64] fp16 (Kh,Kl,Vh), row 144B. Triple buffer,
// one __syncthreads per key tile.
// =====================================================================
#define KVTILE  (64 * 144)     // 9216
#define KVSTAGE (3 * KVTILE)   // 27648
#define FL_SMEM (3 * KVSTAGE)  // 82944

__device__ __forceinline__ void kv_prefetch(
    uint32_t sbs, int kt2,
    const __half* Kh, const __half* Kl, const __half* Vh, int tid)
{
    const size_t rowoff = (size_t)kt2 * 64;
    #pragma unroll
    for (int t = 0; t < 3; t++) {
        const __half* src = (t == 0) ? Kh : (t == 1) ? Kl : Vh;
        #pragma unroll
        for (int i = 0; i < 2; i++) {
            int cc  = i * 256 + tid;     // 0..511
            int row = cc >> 3, seg = cc & 7;
            cp16(sbs + t * KVTILE + row * 144 + seg * 16,
                 src + (rowoff + row) * En + seg * 8);
        }
    }
}

__global__ void __launch_bounds__(256) flash_mma()
{
    extern __shared__ char smc[];
    const uint32_t sb = smem_u32(smc);
    const int tid = threadIdx.x, lane = tid & 31, wp = tid >> 5;
    const int g = lane >> 2, tg = lane & 3;
    const int qt = (int)gridDim.x - 1 - (int)blockIdx.x;   // big tiles first
    const int bh = blockIdx.y, bb = bh >> 4, hh = bh & 15;

    const size_t headoff = (size_t)bb * Tn * En + hh * HSn;
    const __half* Kh = g_Kh + headoff;
    const __half* Kl = g_Kl + headoff;
    const __half* Vh = g_Vh + headoff;

    const int nk = 2 * (qt + 1);   // always >= 2

    kv_prefetch(sb, 0, Kh, Kl, Vh, tid);
    CP_COMMIT();
    kv_prefetch(sb + KVSTAGE, 1, Kh, Kl, Vh, tid);
    CP_COMMIT();

    // Q fragments (fp16 hi only), loaded straight from gmem in frag layout
    uint32_t qh[4][4];
    {
        const size_t q0 = (size_t)(bb * Tn + qt * 128 + wp * 16 + g) * En
                        + hh * HSn;
        const size_t q1 = q0 + (size_t)8 * En;
        #pragma unroll
        for (int kk = 0; kk < 4; kk++) {
            const int c0 = kk * 16 + tg * 2, c1 = c0 + 8;
            qh[kk][0] = *(const uint32_t*)&g_Qh[q0 + c0];
            qh[kk][1] = *(const uint32_t*)&g_Qh[q1 + c0];
            qh[kk][2] = *(const uint32_t*)&g_Qh[q0 + c1];
            qh[kk][3] = *(const uint32_t*)&g_Qh[q1 + c1];
        }
    }

    float o[8][4];
    #pragma unroll
    for (int i = 0; i < 8; i++)
        #pragma unroll
        for (int e = 0; e < 4; e++) o[i][e] = 0.f;
    float m0 = -1e30f, m1 = -1e30f, l0 = 0.f, l1 = 0.f;
    const int qrow0 = qt * 128 + wp * 16 + g, qrow1 = qrow0 + 8;

    const uint32_t kboff = (((lane & 16) >> 1) + (lane & 7)) * 144
                         + ((lane & 8) ? 16 : 0);

    uint32_t bufc = 0, bufp = 2;
    for (int kt = 0; kt < nk; kt++) {
        CP_WAIT1();
        __syncthreads();
        if (kt + 2 < nk) {
            kv_prefetch(sb + bufp * KVSTAGE, kt + 2, Kh, Kl, Vh, tid);
            CP_COMMIT();
        }
        const uint32_t s0 = sb + bufc * KVSTAGE;
        bufc = (bufc == 2) ? 0 : bufc + 1;
        bufp = (bufp == 2) ? 0 : bufp + 1;
        const uint32_t kmh = s0, kml = s0 + KVTILE, vmh = s0 + 2 * KVTILE;

        // ---- S = Qh (Kh+Kl)^T, 8 n8-tiles of 64 keys
        float s[8][4];
        #pragma unroll
        for (int i = 0; i < 8; i++)
            #pragma unroll
            for (int e = 0; e < 4; e++) s[i][e] = 0.f;

        #pragma unroll
        for (int kk = 0; kk < 4; kk++) {
            uint32_t kbh[4][4], kbl[4][4];
            #pragma unroll
            for (int n4 = 0; n4 < 4; n4++) {
                const uint32_t r = n4 * 16 * 144 + kboff + kk * 32;
                ldsm_x4(kbh[n4], kmh + r);
                ldsm_x4(kbl[n4], kml + r);
            }
            #pragma unroll
            for (int nj = 0; nj < 8; nj++)
                mma_f16(s[nj], qh[kk], &kbh[nj >> 1][(nj & 1) * 2]);
            #pragma unroll
            for (int nj = 0; nj < 8; nj++)
                mma_f16(s[nj], qh[kk], &kbl[nj >> 1][(nj & 1) * 2]);
        }

        // ---- causal mask (diagonal tiles only)
        if (kt * 64 + 63 > qrow0) {
            #pragma unroll
            for (int nj = 0; nj < 8; nj++)
                #pragma unroll
                for (int e = 0; e < 4; e++) {
                    const int key = kt * 64 + nj * 8 + tg * 2 + (e & 1);
                    const int qr  = (e < 2) ? qrow0 : qrow1;
                    if (key > qr) s[nj][e] = -1e30f;
                }
        }

        // ---- online softmax (rows g and g+8)
        float mx0 = -1e30f, mx1 = -1e30f;
        #pragma unroll
        for (int nj = 0; nj < 8; nj++) {
            mx0 = fmaxf(mx0, fmaxf(s[nj][0], s[nj][1]));
            mx1 = fmaxf(mx1, fmaxf(s[nj][2], s[nj][3]));
        }
        mx0 = fmaxf(mx0, __shfl_xor_sync(0xffffffffu, mx0, 1));
        mx0 = fmaxf(mx0, __shfl_xor_sync(0xffffffffu, mx0, 2));
        mx1 = fmaxf(mx1, __shfl_xor_sync(0xffffffffu, mx1, 1));
        mx1 = fmaxf(mx1, __shfl_xor_sync(0xffffffffu, mx1, 2));
        const float mn0 = fmaxf(m0, mx0), mn1 = fmaxf(m1, mx1);
        const float a0 = __expf(m0 - mn0), a1 = __expf(m1 - mn1);
        m0 = mn0; m1 = mn1;
        float su0 = 0.f, su1 = 0.f;
        #pragma unroll
        for (int nj = 0; nj < 8; nj++) {
            s[nj][0] = __expf(s[nj][0] - mn0); su0 += s[nj][0];
            s[nj][1] = __expf(s[nj][1] - mn0); su0 += s[nj][1];
            s[nj][2] = __expf(s[nj][2] - mn1); su1 += s[nj][2];
            s[nj][3] = __expf(s[nj][3] - mn1); su1 += s[nj][3];
        }
        su0 += __shfl_xor_sync(0xffffffffu, su0, 1);
        su0 += __shfl_xor_sync(0xffffffffu, su0, 2);
        su1 += __shfl_xor_sync(0xffffffffu, su1, 1);
        su1 += __shfl_xor_sync(0xffffffffu, su1, 2);
        l0 = l0 * a0 + su0; l1 = l1 * a1 + su1;
        #pragma unroll
        for (int nj = 0; nj < 8; nj++) {
            o[nj][0] *= a0; o[nj][1] *= a0; o[nj][2] *= a1; o[nj][3] *= a1;
        }

        // ---- O += Ph Vh
        #pragma unroll
        for (int kk = 0; kk < 4; kk++) {
            uint32_t pah[4];
            {
                const float* p0 = s[2 * kk];
                const float* p1 = s[2 * kk + 1];
                pah[0] = packh(__float2half(p0[0]), __float2half(p0[1]));
                pah[1] = packh(__float2half(p0[2]), __float2half(p0[3]));
                pah[2] = packh(__float2half(p1[0]), __float2half(p1[1]));
                pah[3] = packh(__float2half(p1[2]), __float2half(p1[3]));
            }
            uint32_t vbh[4][4];
            const uint32_t voff = (kk * 16 + (lane & 15)) * 144
                                + ((lane & 16) ? 16 : 0);
            #pragma unroll
            for (int nb = 0; nb < 4; nb++)
                ldsm_x4_t(vbh[nb], vmh + voff + nb * 32);
            #pragma unroll
            for (int nd = 0; nd < 8; nd++)
                mma_f16(o[nd], pah, &vbh[nd >> 1][(nd & 1) * 2]);
        }
    }

    // ---- epilogue: normalize, fp16 store into g_Ah
    const float i0 = 1.f / l0, i1 = 1.f / l1;
    const size_t r0 = (size_t)(bb * Tn + qrow0) * En + hh * HSn;
    const size_t r1 = r0 + (size_t)8 * En;
    #pragma unroll
    for (int nd = 0; nd < 8; nd++) {
        const int col = nd * 8 + tg * 2;
        *(uint32_t*)&g_Ah[r0 + col] =
            packh(__float2half(o[nd][0] * i0), __float2half(o[nd][1] * i0));
        *(uint32_t*)&g_Ah[r1 + col] =
            packh(__float2half(o[nd][2] * i1), __float2half(o[nd][3] * i1));
    }
}

// =====================================================================
extern "C" void kernel_launch(void* const* d_in, const int* in_sizes, int n_in,
                              void* d_out, int out_size)
{
    (void)in_sizes; (void)n_in; (void)out_size;
    const float* X  = (const float*)d_in[0];
    const float* Wq = (const float*)d_in[1];
    const float* bq = (const float*)d_in[2];
    const float* Wk = (const float*)d_in[3];
    const float* bk = (const float*)d_in[4];
    const float* Wv = (const float*)d_in[5];
    const float* bv = (const float*)d_in[6];
    const float* Wo = (const float*)d_in[7];
    const float* bo = (const float*)d_in[8];
    float* out = (float*)d_out;

    cudaFuncSetAttribute(gemm_qkv,
                         cudaFuncAttributeMaxDynamicSharedMemorySize, GEMM_SMEM);
    cudaFuncSetAttribute(gemm_out,
                         cudaFuncAttributeMaxDynamicSharedMemorySize, GEMM_SMEM);
    cudaFuncSetAttribute(flash_mma,
                         cudaFuncAttributeMaxDynamicSharedMemorySize, FL_SMEM);

    dim3 blk(256);
    split_all<<<8192, 256>>>(X, Wq, Wk, Wv, Wo);
    gemm_qkv<<<dim3(En / 128, Mn / 128, 3), blk, GEMM_SMEM>>>(bq, bk, bv);
    flash_mma<<<dim3(Tn / 128, Bn * NHn), blk, FL_SMEM>>>();
    gemm_out<<<dim3(En / 128, Mn / 128), blk, GEMM_SMEM>>>(bo, out);
}

// round 8
// speedup vs baseline: 2.0458x; 1.3308x over previous
#include <cuda_runtime.h>
#include <cuda_fp16.h>
#include <cstdint>

// Problem constants
#define Bn  2
#define Tn  2048
#define En  1024
#define NHn 16
#define HSn 64
#define Mn  (Bn * Tn)        // 4096 token rows

// ---------------- scratch (device globals; no allocation) ----------------
// fp16 scheme: X, all weights, Q, V, attnOut stored fp16-only.
// K stored as fp16 hi/lo pair (flash S-computation keeps 2-pass precision).
__device__ __half g_Xh[(size_t)Mn * En];
__device__ __half g_Wqh[(size_t)En * En];
__device__ __half g_Wkh[(size_t)En * En];
__device__ __half g_Wvh[(size_t)En * En];
__device__ __half g_Woh[(size_t)En * En];
__device__ __half g_Qh[(size_t)Mn * En];   // pre-scaled by 1/8
__device__ __half g_Kh[(size_t)Mn * En];
__device__ __half g_Kl[(size_t)Mn * En];
__device__ __half g_Vh[(size_t)Mn * En];
__device__ __half g_Ah[(size_t)Mn * En];

// =====================================================================
// Baseline-PTX helpers
// =====================================================================
__device__ __forceinline__ uint32_t smem_u32(const void* p) {
    uint32_t a;
    asm("{ .reg .u64 t; cvta.to.shared.u64 t, %1; cvt.u32.u64 %0, t; }"
        : "=r"(a) : "l"(p));
    return a;
}

__device__ __forceinline__ void mma_f16(float* d, const uint32_t* a,
                                        const uint32_t* b) {
    asm volatile(
        "mma.sync.aligned.m16n8k16.row.col.f32.f16.f16.f32 "
        "{%0,%1,%2,%3}, {%4,%5,%6,%7}, {%8,%9}, {%0,%1,%2,%3};\n"
        : "+f"(d[0]), "+f"(d[1]), "+f"(d[2]), "+f"(d[3])
        : "r"(a[0]), "r"(a[1]), "r"(a[2]), "r"(a[3]), "r"(b[0]), "r"(b[1]));
}

__device__ __forceinline__ void ldsm_x4(uint32_t* r, uint32_t a) {
    asm volatile("ldmatrix.sync.aligned.m8n8.x4.shared.b16 {%0,%1,%2,%3}, [%4];"
                 : "=r"(r[0]), "=r"(r[1]), "=r"(r[2]), "=r"(r[3]) : "r"(a));
}
__device__ __forceinline__ void ldsm_x4_t(uint32_t* r, uint32_t a) {
    asm volatile("ldmatrix.sync.aligned.m8n8.x4.trans.shared.b16 {%0,%1,%2,%3}, [%4];"
                 : "=r"(r[0]), "=r"(r[1]), "=r"(r[2]), "=r"(r[3]) : "r"(a));
}

__device__ __forceinline__ void cp16(uint32_t d, const void* g) {
    asm volatile("cp.async.cg.shared.global [%0], [%1], 16;" :: "r"(d), "l"(g));
}
#define CP_COMMIT() asm volatile("cp.async.commit_group;" ::: "memory")
#define CP_WAIT0()  asm volatile("cp.async.wait_group 0;" ::: "memory")
#define CP_WAIT1()  asm volatile("cp.async.wait_group 1;" ::: "memory")

__device__ __forceinline__ uint32_t packh(__half a, __half b) {
    __half2 t(a, b);
    return *reinterpret_cast<uint32_t*>(&t);
}

// =====================================================================
// Fused split kernel: X + all weights -> fp16 (single precision level).
// =====================================================================
__global__ void __launch_bounds__(256) split_all(
    const float* __restrict__ X,  const float* __restrict__ Wq,
    const float* __restrict__ Wk, const float* __restrict__ Wv,
    const float* __restrict__ Wo)
{
    const int i = blockIdx.x * blockDim.x + threadIdx.x;   // float4 index
    const float* src; __half* hi; int base;
    if (i < (1 << 20)) {
        src = X; hi = g_Xh; base = i;
    } else {
        const int r = i - (1 << 20);
        const int seg = r >> 18;
        base = r & ((1 << 18) - 1);
        switch (seg) {
            case 0:  src = Wq; hi = g_Wqh; break;
            case 1:  src = Wk; hi = g_Wkh; break;
            case 2:  src = Wv; hi = g_Wvh; break;
            default: src = Wo; hi = g_Woh; break;
        }
    }
    const float4 v = *(const float4*)(src + (size_t)base * 4);
    uint2 hh;
    hh.x = packh(__float2half(v.x), __float2half(v.y));
    hh.y = packh(__float2half(v.z), __float2half(v.w));
    *(uint2*)(hi + (size_t)base * 4) = hh;
}

// =====================================================================
// GEMM: C[128x128] = A * B^T + bias, plain fp16 mma.sync (single pass).
// 256 thr, 8 warps (4m x 2n), k-stage 32, cp.async triple buffer,
// one __syncthreads per stage.
// =====================================================================
#define GTILE  (128 * 80)      // one [128 x 32] fp16 tile (padded rows)
#define GSTAGE (2 * GTILE)     // A, B
#define GEMM_SMEM (3 * GSTAGE) // 61440
#define NSTAGES (En / 32)      // 32

__device__ __forceinline__ void gemm_prefetch(
    uint32_t sbs, const __half* pA0, const __half* pB0, int k0, int tid)
{
    #pragma unroll
    for (int t = 0; t < 2; t++) {
        const __half* s = (t == 0) ? pA0 : pB0;
        #pragma unroll
        for (int i = 0; i < 2; i++) {
            int cc  = i * 256 + tid;       // 0..511
            int row = cc >> 2, seg = cc & 3;
            cp16(sbs + t * GTILE + row * 80 + seg * 16,
                 s + (size_t)row * En + k0 + seg * 8);
        }
    }
}

__device__ __forceinline__ void gemm_core(
    const __half* __restrict__ Ah, const __half* __restrict__ Bh,
    const float* __restrict__ bias, float* __restrict__ outF,
    __half* __restrict__ outH, __half* __restrict__ outL,
    float outScale)
{
    extern __shared__ char smc[];
    const uint32_t sb = smem_u32(smc);
    const int tid = threadIdx.x, lane = tid & 31, wid = tid >> 5;
    const int wm = wid & 3, wn = wid >> 2;
    const int rowBase = blockIdx.y * 128, colBase = blockIdx.x * 128;

    const __half* pA0 = Ah + (size_t)rowBase * En;
    const __half* pB0 = Bh + (size_t)colBase * En;

    float acc[2][8][4];
    #pragma unroll
    for (int i = 0; i < 2; i++)
        #pragma unroll
        for (int j = 0; j < 8; j++)
            #pragma unroll
            for (int e = 0; e < 4; e++) acc[i][j][e] = 0.f;

    gemm_prefetch(sb, pA0, pB0, 0, tid);
    CP_COMMIT();
    gemm_prefetch(sb + GSTAGE, pA0, pB0, 32, tid);
    CP_COMMIT();

    const uint32_t aoff = (lane & 15) * 80 + (lane >> 4) * 16;
    const uint32_t boff = (((lane & 16) >> 1) + (lane & 7)) * 80
                        + ((lane & 8) ? 16 : 0);

    uint32_t bufc = 0, bufp = 2;   // compute buf, prefetch buf (mod-3)
    for (int st = 0; st < NSTAGES; st++) {
        CP_WAIT1();          // stage st landed
        __syncthreads();     // all readers of buf[bufp] done
        if (st + 2 < NSTAGES) {
            gemm_prefetch(sb + bufp * GSTAGE, pA0, pB0, (st + 2) * 32, tid);
            CP_COMMIT();
        }
        const uint32_t s0 = sb + bufc * GSTAGE;
        bufc = (bufc == 2) ? 0 : bufc + 1;
        bufp = (bufp == 2) ? 0 : bufp + 1;
        const uint32_t aH = s0, bH = s0 + GTILE;

        #pragma unroll
        for (int kk = 0; kk < 2; kk++) {
            uint32_t ah[2][4], bh4[4][4];
            #pragma unroll
            for (int mi = 0; mi < 2; mi++)
                ldsm_x4(ah[mi], aH + (wm * 32 + mi * 16) * 80 + aoff + kk * 32);
            #pragma unroll
            for (int n4 = 0; n4 < 4; n4++)
                ldsm_x4(bh4[n4], bH + (wn * 64 + n4 * 16) * 80 + boff + kk * 32);
            #pragma unroll
            for (int mi = 0; mi < 2; mi++)
                #pragma unroll
                for (int nj = 0; nj < 8; nj++)
                    mma_f16(acc[mi][nj], ah[mi], &bh4[nj >> 1][(nj & 1) * 2]);
        }
    }

    // epilogue
    #pragma unroll
    for (int mi = 0; mi < 2; mi++) {
        const int rb = rowBase + wm * 32 + mi * 16 + (lane >> 2);
        #pragma unroll
        for (int half = 0; half < 2; half++) {
            const size_t r = (size_t)(rb + half * 8);
            #pragma unroll
            for (int nj = 0; nj < 8; nj++) {
                const int col = colBase + wn * 64 + nj * 8 + (lane & 3) * 2;
                float v0 = (acc[mi][nj][half * 2 + 0] + bias[col]) * outScale;
                float v1 = (acc[mi][nj][half * 2 + 1] + bias[col + 1]) * outScale;
                if (outF) {
                    *(float2*)&outF[r * En + col] = make_float2(v0, v1);
                } else if (outL) {       // fp16 hi/lo pair (K)
                    __half h0 = __float2half(v0), h1 = __float2half(v1);
                    *(uint32_t*)&outH[r * En + col] = packh(h0, h1);
                    *(uint32_t*)&outL[r * En + col] =
                        packh(__float2half(v0 - __half2float(h0)),
                              __float2half(v1 - __half2float(h1)));
                } else {                 // fp16 only (Q, V, attn out)
                    *(uint32_t*)&outH[r * En + col] =
                        packh(__float2half(v0), __float2half(v1));
                }
            }
        }
    }
}

__global__ void __launch_bounds__(256, 2) gemm_qkv(
    const float* bq, const float* bk, const float* bv)
{
    if (blockIdx.z == 0)
        gemm_core(g_Xh, g_Wqh, bq, nullptr, g_Qh, nullptr, 0.125f);
    else if (blockIdx.z == 1)
        gemm_core(g_Xh, g_Wkh, bk, nullptr, g_Kh, g_Kl, 1.0f);
    else
        gemm_core(g_Xh, g_Wvh, bv, nullptr, g_Vh, nullptr, 1.0f);
}

__global__ void __launch_bounds__(256, 2) gemm_out(const float* bo, float* out)
{
    gemm_core(g_Ah, g_Woh, bo, out, nullptr, nullptr, 1.0f);
}

// =====================================================================
// Flash attention (causal) via mma.sync. Q pre-scaled by 1/8.
// S = Qh*(Kh+Kl)  (2-pass, preserves logit precision);  O = Ph*Vh.
// KV stage: 3 tiles [64x64] fp16 (Kh,Kl,Vh), row 144B. Triple buffer,
// one __syncthreads per key tile.
// =====================================================================
#define KVTILE  (64 * 144)     // 9216
#define KVSTAGE (3 * KVTILE)   // 27648
#define FL_SMEM (3 * KVSTAGE)  // 82944

__device__ __forceinline__ void kv_prefetch(
    uint32_t sbs, int kt2,
    const __half* Kh, const __half* Kl, const __half* Vh, int tid)
{
    const size_t rowoff = (size_t)kt2 * 64;
    #pragma unroll
    for (int t = 0; t < 3; t++) {
        const __half* src = (t == 0) ? Kh : (t == 1) ? Kl : Vh;
        #pragma unroll
        for (int i = 0; i < 2; i++) {
            int cc  = i * 256 + tid;     // 0..511
            int row = cc >> 3, seg = cc & 7;
            cp16(sbs + t * KVTILE + row * 144 + seg * 16,
                 src + (rowoff + row) * En + seg * 8);
        }
    }
}

__global__ void __launch_bounds__(256) flash_mma()
{
    extern __shared__ char smc[];
    const uint32_t sb = smem_u32(smc);
    const int tid = threadIdx.x, lane = tid & 31, wp = tid >> 5;
    const int g = lane >> 2, tg = lane & 3;
    const int qt = (int)gridDim.x - 1 - (int)blockIdx.x;   // big tiles first
    const int bh = blockIdx.y, bb = bh >> 4, hh = bh & 15;

    const size_t headoff = (size_t)bb * Tn * En + hh * HSn;
    const __half* Kh = g_Kh + headoff;
    const __half* Kl = g_Kl + headoff;
    const __half* Vh = g_Vh + headoff;

    const int nk = 2 * (qt + 1);   // always >= 2

    kv_prefetch(sb, 0, Kh, Kl, Vh, tid);
    CP_COMMIT();
    kv_prefetch(sb + KVSTAGE, 1, Kh, Kl, Vh, tid);
    CP_COMMIT();

    // Q fragments (fp16), loaded straight from gmem in frag layout
    uint32_t qh[4][4];
    {
        const size_t q0 = (size_t)(bb * Tn + qt * 128 + wp * 16 + g) * En
                        + hh * HSn;
        const size_t q1 = q0 + (size_t)8 * En;
        #pragma unroll
        for (int kk = 0; kk < 4; kk++) {
            const int c0 = kk * 16 + tg * 2, c1 = c0 + 8;
            qh[kk][0] = *(const uint32_t*)&g_Qh[q0 + c0];
            qh[kk][1] = *(const uint32_t*)&g_Qh[q1 + c0];
            qh[kk][2] = *(const uint32_t*)&g_Qh[q0 + c1];
            qh[kk][3] = *(const uint32_t*)&g_Qh[q1 + c1];
        }
    }

    float o[8][4];
    #pragma unroll
    for (int i = 0; i < 8; i++)
        #pragma unroll
        for (int e = 0; e < 4; e++) o[i][e] = 0.f;
    float m0 = -1e30f, m1 = -1e30f, l0 = 0.f, l1 = 0.f;
    const int qrow0 = qt * 128 + wp * 16 + g, qrow1 = qrow0 + 8;

    const uint32_t kboff = (((lane & 16) >> 1) + (lane & 7)) * 144
                         + ((lane & 8) ? 16 : 0);

    uint32_t bufc = 0, bufp = 2;
    for (int kt = 0; kt < nk; kt++) {
        CP_WAIT1();
        __syncthreads();
        if (kt + 2 < nk) {
            kv_prefetch(sb + bufp * KVSTAGE, kt + 2, Kh, Kl, Vh, tid);
            CP_COMMIT();
        }
        const uint32_t s0 = sb + bufc * KVSTAGE;
        bufc = (bufc == 2) ? 0 : bufc + 1;
        bufp = (bufp == 2) ? 0 : bufp + 1;
        const uint32_t kmh = s0, kml = s0 + KVTILE, vmh = s0 + 2 * KVTILE;

        // ---- S = Qh (Kh+Kl)^T, 8 n8-tiles of 64 keys
        float s[8][4];
        #pragma unroll
        for (int i = 0; i < 8; i++)
            #pragma unroll
            for (int e = 0; e < 4; e++) s[i][e] = 0.f;

        #pragma unroll
        for (int kk = 0; kk < 4; kk++) {
            uint32_t kbh[4][4], kbl[4][4];
            #pragma unroll
            for (int n4 = 0; n4 < 4; n4++) {
                const uint32_t r = n4 * 16 * 144 + kboff + kk * 32;
                ldsm_x4(kbh[n4], kmh + r);
                ldsm_x4(kbl[n4], kml + r);
            }
            #pragma unroll
            for (int nj = 0; nj < 8; nj++)
                mma_f16(s[nj], qh[kk], &kbh[nj >> 1][(nj & 1) * 2]);
            #pragma unroll
            for (int nj = 0; nj < 8; nj++)
                mma_f16(s[nj], qh[kk], &kbl[nj >> 1][(nj & 1) * 2]);
        }

        // ---- causal mask (diagonal tiles only)
        if (kt * 64 + 63 > qrow0) {
            #pragma unroll
            for (int nj = 0; nj < 8; nj++)
                #pragma unroll
                for (int e = 0; e < 4; e++) {
                    const int key = kt * 64 + nj * 8 + tg * 2 + (e & 1);
                    const int qr  = (e < 2) ? qrow0 : qrow1;
                    if (key > qr) s[nj][e] = -1e30f;
                }
        }

        // ---- online softmax (rows g and g+8)
        float mx0 = -1e30f, mx1 = -1e30f;
        #pragma unroll
        for (int nj = 0; nj < 8; nj++) {
            mx0 = fmaxf(mx0, fmaxf(s[nj][0], s[nj][1]));
            mx1 = fmaxf(mx1, fmaxf(s[nj][2], s[nj][3]));
        }
        mx0 = fmaxf(mx0, __shfl_xor_sync(0xffffffffu, mx0, 1));
        mx0 = fmaxf(mx0, __shfl_xor_sync(0xffffffffu, mx0, 2));
        mx1 = fmaxf(mx1, __shfl_xor_sync(0xffffffffu, mx1, 1));
        mx1 = fmaxf(mx1, __shfl_xor_sync(0xffffffffu, mx1, 2));
        const float mn0 = fmaxf(m0, mx0), mn1 = fmaxf(m1, mx1);
        const float a0 = __expf(m0 - mn0), a1 = __expf(m1 - mn1);
        m0 = mn0; m1 = mn1;
        float su0 = 0.f, su1 = 0.f;
        #pragma unroll
        for (int nj = 0; nj < 8; nj++) {
            s[nj][0] = __expf(s[nj][0] - mn0); su0 += s[nj][0];
            s[nj][1] = __expf(s[nj][1] - mn0); su0 += s[nj][1];
            s[nj][2] = __expf(s[nj][2] - mn1); su1 += s[nj][2];
            s[nj][3] = __expf(s[nj][3] - mn1); su1 += s[nj][3];
        }
        su0 += __shfl_xor_sync(0xffffffffu, su0, 1);
        su0 += __shfl_xor_sync(0xffffffffu, su0, 2);
        su1 += __shfl_xor_sync(0xffffffffu, su1, 1);
        su1 += __shfl_xor_sync(0xffffffffu, su1, 2);
        l0 = l0 * a0 + su0; l1 = l1 * a1 + su1;
        #pragma unroll
        for (int nj = 0; nj < 8; nj++) {
            o[nj][0] *= a0; o[nj][1] *= a0; o[nj][2] *= a1; o[nj][3] *= a1;
        }

        // ---- O += Ph Vh
        #pragma unroll
        for (int kk = 0; kk < 4; kk++) {
            uint32_t pah[4];
            {
                const float* p0 = s[2 * kk];
                const float* p1 = s[2 * kk + 1];
                pah[0] = packh(__float2half(p0[0]), __float2half(p0[1]));
                pah[1] = packh(__float2half(p0[2]), __float2half(p0[3]));
                pah[2] = packh(__float2half(p1[0]), __float2half(p1[1]));
                pah[3] = packh(__float2half(p1[2]), __float2half(p1[3]));
            }
            uint32_t vbh[4][4];
            const uint32_t voff = (kk * 16 + (lane & 15)) * 144
                                + ((lane & 16) ? 16 : 0);
            #pragma unroll
            for (int nb = 0; nb < 4; nb++)
                ldsm_x4_t(vbh[nb], vmh + voff + nb * 32);
            #pragma unroll
            for (int nd = 0; nd < 8; nd++)
                mma_f16(o[nd], pah, &vbh[nd >> 1][(nd & 1) * 2]);
        }
    }

    // ---- epilogue: normalize, fp16 store into g_Ah
    const float i0 = 1.f / l0, i1 = 1.f / l1;
    const size_t r0 = (size_t)(bb * Tn + qrow0) * En + hh * HSn;
    const size_t r1 = r0 + (size_t)8 * En;
    #pragma unroll
    for (int nd = 0; nd < 8; nd++) {
        const int col = nd * 8 + tg * 2;
        *(uint32_t*)&g_Ah[r0 + col] =
            packh(__float2half(o[nd][0] * i0), __float2half(o[nd][1] * i0));
        *(uint32_t*)&g_Ah[r1 + col] =
            packh(__float2half(o[nd][2] * i1), __float2half(o[nd][3] * i1));
    }
}

// =====================================================================
extern "C" void kernel_launch(void* const* d_in, const int* in_sizes, int n_in,
                              void* d_out, int out_size)
{
    (void)in_sizes; (void)n_in; (void)out_size;
    const float* X  = (const float*)d_in[0];
    const float* Wq = (const float*)d_in[1];
    const float* bq = (const float*)d_in[2];
    const float* Wk = (const float*)d_in[3];
    const float* bk = (const float*)d_in[4];
    const float* Wv = (const float*)d_in[5];
    const float* bv = (const float*)d_in[6];
    const float* Wo = (const float*)d_in[7];
    const float* bo = (const float*)d_in[8];
    float* out = (float*)d_out;

    cudaFuncSetAttribute(gemm_qkv,
                         cudaFuncAttributeMaxDynamicSharedMemorySize, GEMM_SMEM);
    cudaFuncSetAttribute(gemm_out,
                         cudaFuncAttributeMaxDynamicSharedMemorySize, GEMM_SMEM);
    cudaFuncSetAttribute(flash_mma,
                         cudaFuncAttributeMaxDynamicSharedMemorySize, FL_SMEM);

    dim3 blk(256);
    split_all<<<8192, 256>>>(X, Wq, Wk, Wv, Wo);
    gemm_qkv<<<dim3(En / 128, Mn / 128, 3), blk, GEMM_SMEM>>>(bq, bk, bv);
    flash_mma<<<dim3(Tn / 128, Bn * NHn), blk, FL_SMEM>>>();
    gemm_out<<<dim3(En / 128, Mn / 128), blk, GEMM_SMEM>>>(bo, out);
}

// round 9
// speedup vs baseline: 2.3505x; 1.1489x over previous
#include <cuda_runtime.h>
#include <cuda_fp16.h>
#include <cstdint>

// Problem constants
#define Bn  2
#define Tn  2048
#define En  1024
#define NHn 16
#define HSn 64
#define Mn  (Bn * Tn)        // 4096 token rows

// ---------------- scratch (device globals; no allocation) ----------------
// All intermediate tensors fp16 (single level). Error model keeps total
// rel_err ~4.3e-4 vs the 1e-3 gate (see round notes).
__device__ __half g_Xh[(size_t)Mn * En];
__device__ __half g_Wqh[(size_t)En * En];
__device__ __half g_Wkh[(size_t)En * En];
__device__ __half g_Wvh[(size_t)En * En];
__device__ __half g_Woh[(size_t)En * En];
__device__ __half g_Qh[(size_t)Mn * En];   // pre-scaled by 1/8
__device__ __half g_Kh[(size_t)Mn * En];
__device__ __half g_Vh[(size_t)Mn * En];
__device__ __half g_Ah[(size_t)Mn * En];

// =====================================================================
// Baseline-PTX helpers
// =====================================================================
__device__ __forceinline__ uint32_t smem_u32(const void* p) {
    uint32_t a;
    asm("{ .reg .u64 t; cvta.to.shared.u64 t, %1; cvt.u32.u64 %0, t; }"
        : "=r"(a) : "l"(p));
    return a;
}

__device__ __forceinline__ void mma_f16(float* d, const uint32_t* a,
                                        const uint32_t* b) {
    asm volatile(
        "mma.sync.aligned.m16n8k16.row.col.f32.f16.f16.f32 "
        "{%0,%1,%2,%3}, {%4,%5,%6,%7}, {%8,%9}, {%0,%1,%2,%3};\n"
        : "+f"(d[0]), "+f"(d[1]), "+f"(d[2]), "+f"(d[3])
        : "r"(a[0]), "r"(a[1]), "r"(a[2]), "r"(a[3]), "r"(b[0]), "r"(b[1]));
}

__device__ __forceinline__ void ldsm_x4(uint32_t* r, uint32_t a) {
    asm volatile("ldmatrix.sync.aligned.m8n8.x4.shared.b16 {%0,%1,%2,%3}, [%4];"
                 : "=r"(r[0]), "=r"(r[1]), "=r"(r[2]), "=r"(r[3]) : "r"(a));
}
__device__ __forceinline__ void ldsm_x4_t(uint32_t* r, uint32_t a) {
    asm volatile("ldmatrix.sync.aligned.m8n8.x4.trans.shared.b16 {%0,%1,%2,%3}, [%4];"
                 : "=r"(r[0]), "=r"(r[1]), "=r"(r[2]), "=r"(r[3]) : "r"(a));
}

__device__ __forceinline__ void cp16(uint32_t d, const void* g) {
    asm volatile("cp.async.cg.shared.global [%0], [%1], 16;" :: "r"(d), "l"(g));
}
#define CP_COMMIT() asm volatile("cp.async.commit_group;" ::: "memory")
#define CP_WAIT0()  asm volatile("cp.async.wait_group 0;" ::: "memory")
#define CP_WAIT1()  asm volatile("cp.async.wait_group 1;" ::: "memory")

__device__ __forceinline__ uint32_t packh(__half a, __half b) {
    __half2 t(a, b);
    return *reinterpret_cast<uint32_t*>(&t);
}

// =====================================================================
// Fused split kernel: X + all weights -> fp16.
// =====================================================================
__global__ void __launch_bounds__(256) split_all(
    const float* __restrict__ X,  const float* __restrict__ Wq,
    const float* __restrict__ Wk, const float* __restrict__ Wv,
    const float* __restrict__ Wo)
{
    const int i = blockIdx.x * blockDim.x + threadIdx.x;   // float4 index
    const float* src; __half* hi; int base;
    if (i < (1 << 20)) {
        src = X; hi = g_Xh; base = i;
    } else {
        const int r = i - (1 << 20);
        const int seg = r >> 18;
        base = r & ((1 << 18) - 1);
        switch (seg) {
            case 0:  src = Wq; hi = g_Wqh; break;
            case 1:  src = Wk; hi = g_Wkh; break;
            case 2:  src = Wv; hi = g_Wvh; break;
            default: src = Wo; hi = g_Woh; break;
        }
    }
    const float4 v = *(const float4*)(src + (size_t)base * 4);
    uint2 hh;
    hh.x = packh(__float2half(v.x), __float2half(v.y));
    hh.y = packh(__float2half(v.z), __float2half(v.w));
    *(uint2*)(hi + (size_t)base * 4) = hh;
}

// =====================================================================
// GEMM: C[128x128] = A * B^T + bias, plain fp16 mma.sync (single pass).
// 256 thr, 8 warps (4m x 2n), k-stage 32, cp.async triple buffer,
// one __syncthreads per stage.
// =====================================================================
#define GTILE  (128 * 80)      // one [128 x 32] fp16 tile (padded rows)
#define GSTAGE (2 * GTILE)     // A, B
#define GEMM_SMEM (3 * GSTAGE) // 61440
#define NSTAGES (En / 32)      // 32

__device__ __forceinline__ void gemm_prefetch(
    uint32_t sbs, const __half* pA0, const __half* pB0, int k0, int tid)
{
    #pragma unroll
    for (int t = 0; t < 2; t++) {
        const __half* s = (t == 0) ? pA0 : pB0;
        #pragma unroll
        for (int i = 0; i < 2; i++) {
            int cc  = i * 256 + tid;       // 0..511
            int row = cc >> 2, seg = cc & 3;
            cp16(sbs + t * GTILE + row * 80 + seg * 16,
                 s + (size_t)row * En + k0 + seg * 8);
        }
    }
}

__device__ __forceinline__ void gemm_core(
    const __half* __restrict__ Ah, const __half* __restrict__ Bh,
    const float* __restrict__ bias, float* __restrict__ outF,
    __half* __restrict__ outH, float outScale)
{
    extern __shared__ char smc[];
    const uint32_t sb = smem_u32(smc);
    const int tid = threadIdx.x, lane = tid & 31, wid = tid >> 5;
    const int wm = wid & 3, wn = wid >> 2;
    const int rowBase = blockIdx.y * 128, colBase = blockIdx.x * 128;

    const __half* pA0 = Ah + (size_t)rowBase * En;
    const __half* pB0 = Bh + (size_t)colBase * En;

    float acc[2][8][4];
    #pragma unroll
    for (int i = 0; i < 2; i++)
        #pragma unroll
        for (int j = 0; j < 8; j++)
            #pragma unroll
            for (int e = 0; e < 4; e++) acc[i][j][e] = 0.f;

    gemm_prefetch(sb, pA0, pB0, 0, tid);
    CP_COMMIT();
    gemm_prefetch(sb + GSTAGE, pA0, pB0, 32, tid);
    CP_COMMIT();

    const uint32_t aoff = (lane & 15) * 80 + (lane >> 4) * 16;
    const uint32_t boff = (((lane & 16) >> 1) + (lane & 7)) * 80
                        + ((lane & 8) ? 16 : 0);

    uint32_t bufc = 0, bufp = 2;   // compute buf, prefetch buf (mod-3)
    for (int st = 0; st < NSTAGES; st++) {
        CP_WAIT1();          // stage st landed
        __syncthreads();     // all readers of buf[bufp] done
        if (st + 2 < NSTAGES) {
            gemm_prefetch(sb + bufp * GSTAGE, pA0, pB0, (st + 2) * 32, tid);
            CP_COMMIT();
        }
        const uint32_t s0 = sb + bufc * GSTAGE;
        bufc = (bufc == 2) ? 0 : bufc + 1;
        bufp = (bufp == 2) ? 0 : bufp + 1;
        const uint32_t aH = s0, bH = s0 + GTILE;

        #pragma unroll
        for (int kk = 0; kk < 2; kk++) {
            uint32_t ah[2][4], bh4[4][4];
            #pragma unroll
            for (int mi = 0; mi < 2; mi++)
                ldsm_x4(ah[mi], aH + (wm * 32 + mi * 16) * 80 + aoff + kk * 32);
            #pragma unroll
            for (int n4 = 0; n4 < 4; n4++)
                ldsm_x4(bh4[n4], bH + (wn * 64 + n4 * 16) * 80 + boff + kk * 32);
            #pragma unroll
            for (int mi = 0; mi < 2; mi++)
                #pragma unroll
                for (int nj = 0; nj < 8; nj++)
                    mma_f16(acc[mi][nj], ah[mi], &bh4[nj >> 1][(nj & 1) * 2]);
        }
    }

    // epilogue
    #pragma unroll
    for (int mi = 0; mi < 2; mi++) {
        const int rb = rowBase + wm * 32 + mi * 16 + (lane >> 2);
        #pragma unroll
        for (int half = 0; half < 2; half++) {
            const size_t r = (size_t)(rb + half * 8);
            #pragma unroll
            for (int nj = 0; nj < 8; nj++) {
                const int col = colBase + wn * 64 + nj * 8 + (lane & 3) * 2;
                float v0 = (acc[mi][nj][half * 2 + 0] + bias[col]) * outScale;
                float v1 = (acc[mi][nj][half * 2 + 1] + bias[col + 1]) * outScale;
                if (outF) {
                    *(float2*)&outF[r * En + col] = make_float2(v0, v1);
                } else {
                    *(uint32_t*)&outH[r * En + col] =
                        packh(__float2half(v0), __float2half(v1));
                }
            }
        }
    }
}

__global__ void __launch_bounds__(256, 2) gemm_qkv(
    const float* bq, const float* bk, const float* bv)
{
    if (blockIdx.z == 0)
        gemm_core(g_Xh, g_Wqh, bq, nullptr, g_Qh, 0.125f);
    else if (blockIdx.z == 1)
        gemm_core(g_Xh, g_Wkh, bk, nullptr, g_Kh, 1.0f);
    else
        gemm_core(g_Xh, g_Wvh, bv, nullptr, g_Vh, 1.0f);
}

__global__ void __launch_bounds__(256, 2) gemm_out(const float* bo, float* out)
{
    gemm_core(g_Ah, g_Woh, bo, out, nullptr, 1.0f);
}

// =====================================================================
// Flash attention (causal) via mma.sync fp16. Q pre-scaled by 1/8.
// S = Qh*Kh (single pass);  O = Ph*Vh.
// KV stage: 2 tiles [64x64] fp16 (Kh,Vh), row 144B. Triple buffer,
// one __syncthreads per key tile. 2 CTAs/SM.
// =====================================================================
#define KVTILE  (64 * 144)     // 9216
#define KVSTAGE (2 * KVTILE)   // 18432
#define FL_SMEM (3 * KVSTAGE)  // 55296

__device__ __forceinline__ void kv_prefetch(
    uint32_t sbs, int kt2, const __half* Kh, const __half* Vh, int tid)
{
    const size_t rowoff = (size_t)kt2 * 64;
    #pragma unroll
    for (int t = 0; t < 2; t++) {
        const __half* src = (t == 0) ? Kh : Vh;
        #pragma unroll
        for (int i = 0; i < 2; i++) {
            int cc  = i * 256 + tid;     // 0..511
            int row = cc >> 3, seg = cc & 7;
            cp16(sbs + t * KVTILE + row * 144 + seg * 16,
                 src + (rowoff + row) * En + seg * 8);
        }
    }
}

__global__ void __launch_bounds__(256, 2) flash_mma()
{
    extern __shared__ char smc[];
    const uint32_t sb = smem_u32(smc);
    const int tid = threadIdx.x, lane = tid & 31, wp = tid >> 5;
    const int g = lane >> 2, tg = lane & 3;
    const int qt = (int)gridDim.x - 1 - (int)blockIdx.x;   // big tiles first
    const int bh = blockIdx.y, bb = bh >> 4, hh = bh & 15;

    const size_t headoff = (size_t)bb * Tn * En + hh * HSn;
    const __half* Kh = g_Kh + headoff;
    const __half* Vh = g_Vh + headoff;

    const int nk = 2 * (qt + 1);   // always >= 2

    kv_prefetch(sb, 0, Kh, Vh, tid);
    CP_COMMIT();
    kv_prefetch(sb + KVSTAGE, 1, Kh, Vh, tid);
    CP_COMMIT();

    // Q fragments (fp16), loaded straight from gmem in frag layout
    uint32_t qh[4][4];
    {
        const size_t q0 = (size_t)(bb * Tn + qt * 128 + wp * 16 + g) * En
                        + hh * HSn;
        const size_t q1 = q0 + (size_t)8 * En;
        #pragma unroll
        for (int kk = 0; kk < 4; kk++) {
            const int c0 = kk * 16 + tg * 2, c1 = c0 + 8;
            qh[kk][0] = *(const uint32_t*)&g_Qh[q0 + c0];
            qh[kk][1] = *(const uint32_t*)&g_Qh[q1 + c0];
            qh[kk][2] = *(const uint32_t*)&g_Qh[q0 + c1];
            qh[kk][3] = *(const uint32_t*)&g_Qh[q1 + c1];
        }
    }

    float o[8][4];
    #pragma unroll
    for (int i = 0; i < 8; i++)
        #pragma unroll
        for (int e = 0; e < 4; e++) o[i][e] = 0.f;
    float m0 = -1e30f, m1 = -1e30f, l0 = 0.f, l1 = 0.f;
    const int qrow0 = qt * 128 + wp * 16 + g, qrow1 = qrow0 + 8;

    const uint32_t kboff = (((lane & 16) >> 1) + (lane & 7)) * 144
                         + ((lane & 8) ? 16 : 0);

    uint32_t bufc = 0, bufp = 2;
    for (int kt = 0; kt < nk; kt++) {
        CP_WAIT1();
        __syncthreads();
        if (kt + 2 < nk) {
            kv_prefetch(sb + bufp * KVSTAGE, kt + 2, Kh, Vh, tid);
            CP_COMMIT();
        }
        const uint32_t s0 = sb + bufc * KVSTAGE;
        bufc = (bufc == 2) ? 0 : bufc + 1;
        bufp = (bufp == 2) ? 0 : bufp + 1;
        const uint32_t kmh = s0, vmh = s0 + KVTILE;

        // ---- S = Qh Kh^T, 8 n8-tiles of 64 keys (single pass)
        float s[8][4];
        #pragma unroll
        for (int i = 0; i < 8; i++)
            #pragma unroll
            for (int e = 0; e < 4; e++) s[i][e] = 0.f;

        #pragma unroll
        for (int kk = 0; kk < 4; kk++) {
            uint32_t kbh[4][4];
            #pragma unroll
            for (int n4 = 0; n4 < 4; n4++)
                ldsm_x4(kbh[n4], kmh + n4 * 16 * 144 + kboff + kk * 32);
            #pragma unroll
            for (int nj = 0; nj < 8; nj++)
                mma_f16(s[nj], qh[kk], &kbh[nj >> 1][(nj & 1) * 2]);
        }

        // ---- causal mask (diagonal tiles only)
        if (kt * 64 + 63 > qrow0) {
            #pragma unroll
            for (int nj = 0; nj < 8; nj++)
                #pragma unroll
                for (int e = 0; e < 4; e++) {
                    const int key = kt * 64 + nj * 8 + tg * 2 + (e & 1);
                    const int qr  = (e < 2) ? qrow0 : qrow1;
                    if (key > qr) s[nj][e] = -1e30f;
                }
        }

        // ---- online softmax (rows g and g+8)
        float mx0 = -1e30f, mx1 = -1e30f;
        #pragma unroll
        for (int nj = 0; nj < 8; nj++) {
            mx0 = fmaxf(mx0, fmaxf(s[nj][0], s[nj][1]));
            mx1 = fmaxf(mx1, fmaxf(s[nj][2], s[nj][3]));
        }
        mx0 = fmaxf(mx0, __shfl_xor_sync(0xffffffffu, mx0, 1));
        mx0 = fmaxf(mx0, __shfl_xor_sync(0xffffffffu, mx0, 2));
        mx1 = fmaxf(mx1, __shfl_xor_sync(0xffffffffu, mx1, 1));
        mx1 = fmaxf(mx1, __shfl_xor_sync(0xffffffffu, mx1, 2));
        const float mn0 = fmaxf(m0, mx0), mn1 = fmaxf(m1, mx1);
        const float a0 = __expf(m0 - mn0), a1 = __expf(m1 - mn1);
        m0 = mn0; m1 = mn1;
        float su0 = 0.f, su1 = 0.f;
        #pragma unroll
        for (int nj = 0; nj < 8; nj++) {
            s[nj][0] = __expf(s[nj][0] - mn0); su0 += s[nj][0];
            s[nj][1] = __expf(s[nj][1] - mn0); su0 += s[nj][1];
            s[nj][2] = __expf(s[nj][2] - mn1); su1 += s[nj][2];
            s[nj][3] = __expf(s[nj][3] - mn1); su1 += s[nj][3];
        }
        su0 += __shfl_xor_sync(0xffffffffu, su0, 1);
        su0 += __shfl_xor_sync(0xffffffffu, su0, 2);
        su1 += __shfl_xor_sync(0xffffffffu, su1, 1);
        su1 += __shfl_xor_sync(0xffffffffu, su1, 2);
        l0 = l0 * a0 + su0; l1 = l1 * a1 + su1;
        #pragma unroll
        for (int nj = 0; nj < 8; nj++) {
            o[nj][0] *= a0; o[nj][1] *= a0; o[nj][2] *= a1; o[nj][3] *= a1;
        }

        // ---- O += Ph Vh
        #pragma unroll
        for (int kk = 0; kk < 4; kk++) {
            uint32_t pah[4];
            {
                const float* p0 = s[2 * kk];
                const float* p1 = s[2 * kk + 1];
                pah[0] = packh(__float2half(p0[0]), __float2half(p0[1]));
                pah[1] = packh(__float2half(p0[2]), __float2half(p0[3]));
                pah[2] = packh(__float2half(p1[0]), __float2half(p1[1]));
                pah[3] = packh(__float2half(p1[2]), __float2half(p1[3]));
            }
            uint32_t vbh[4][4];
            const uint32_t voff = (kk * 16 + (lane & 15)) * 144
                                + ((lane & 16) ? 16 : 0);
            #pragma unroll
            for (int nb = 0; nb < 4; nb++)
                ldsm_x4_t(vbh[nb], vmh + voff + nb * 32);
            #pragma unroll
            for (int nd = 0; nd < 8; nd++)
                mma_f16(o[nd], pah, &vbh[nd >> 1][(nd & 1) * 2]);
        }
    }

    // ---- epilogue: normalize, fp16 store into g_Ah
    const float i0 = 1.f / l0, i1 = 1.f / l1;
    const size_t r0 = (size_t)(bb * Tn + qrow0) * En + hh * HSn;
    const size_t r1 = r0 + (size_t)8 * En;
    #pragma unroll
    for (int nd = 0; nd < 8; nd++) {
        const int col = nd * 8 + tg * 2;
        *(uint32_t*)&g_Ah[r0 + col] =
            packh(__float2half(o[nd][0] * i0), __float2half(o[nd][1] * i0));
        *(uint32_t*)&g_Ah[r1 + col] =
            packh(__float2half(o[nd][2] * i1), __float2half(o[nd][3] * i1));
    }
}

// =====================================================================
extern "C" void kernel_launch(void* const* d_in, const int* in_sizes, int n_in,
                              void* d_out, int out_size)
{
    (void)in_sizes; (void)n_in; (void)out_size;
    const float* X  = (const float*)d_in[0];
    const float* Wq = (const float*)d_in[1];
    const float* bq = (const float*)d_in[2];
    const float* Wk = (const float*)d_in[3];
    const float* bk = (const float*)d_in[4];
    const float* Wv = (const float*)d_in[5];
    const float* bv = (const float*)d_in[6];
    const float* Wo = (const float*)d_in[7];
    const float* bo = (const float*)d_in[8];
    float* out = (float*)d_out;

    cudaFuncSetAttribute(gemm_qkv,
                         cudaFuncAttributeMaxDynamicSharedMemorySize, GEMM_SMEM);
    cudaFuncSetAttribute(gemm_out,
                         cudaFuncAttributeMaxDynamicSharedMemorySize, GEMM_SMEM);
    cudaFuncSetAttribute(flash_mma,
                         cudaFuncAttributeMaxDynamicSharedMemorySize, FL_SMEM);

    dim3 blk(256);
    split_all<<<8192, 256>>>(X, Wq, Wk, Wv, Wo);
    gemm_qkv<<<dim3(En / 128, Mn / 128, 3), blk, GEMM_SMEM>>>(bq, bk, bv);
    flash_mma<<<dim3(Tn / 128, Bn * NHn), blk, FL_SMEM>>>();
    gemm_out<<<dim3(En / 128, Mn / 128), blk, GEMM_SMEM>>>(bo, out);
}

// round 10
// speedup vs baseline: 2.5422x; 1.0816x over previous
#include <cuda_runtime.h>
#include <cuda_fp16.h>
#include <cstdint>

// Problem constants
#define Bn  2
#define Tn  2048
#define En  1024
#define NHn 16
#define HSn 64
#define Mn  (Bn * Tn)        // 4096 token rows

// ---------------- scratch (device globals; no allocation) ----------------
__device__ __half g_Xh[(size_t)Mn * En];
__device__ __half g_Wqh[(size_t)En * En];
__device__ __half g_Wkh[(size_t)En * En];
__device__ __half g_Wvh[(size_t)En * En];
__device__ __half g_Woh[(size_t)En * En];
__device__ __half g_Qh[(size_t)Mn * En];   // pre-scaled by 1/8
__device__ __half g_Kh[(size_t)Mn * En];
__device__ __half g_Vh[(size_t)Mn * En];
__device__ __half g_Ah[(size_t)Mn * En];

// =====================================================================
// Baseline-PTX helpers
// =====================================================================
__device__ __forceinline__ uint32_t smem_u32(const void* p) {
    uint32_t a;
    asm("{ .reg .u64 t; cvta.to.shared.u64 t, %1; cvt.u32.u64 %0, t; }"
        : "=r"(a) : "l"(p));
    return a;
}

__device__ __forceinline__ void mma_f16(float* d, const uint32_t* a,
                                        const uint32_t* b) {
    asm volatile(
        "mma.sync.aligned.m16n8k16.row.col.f32.f16.f16.f32 "
        "{%0,%1,%2,%3}, {%4,%5,%6,%7}, {%8,%9}, {%0,%1,%2,%3};\n"
        : "+f"(d[0]), "+f"(d[1]), "+f"(d[2]), "+f"(d[3])
        : "r"(a[0]), "r"(a[1]), "r"(a[2]), "r"(a[3]), "r"(b[0]), "r"(b[1]));
}

__device__ __forceinline__ void ldsm_x4(uint32_t* r, uint32_t a) {
    asm volatile("ldmatrix.sync.aligned.m8n8.x4.shared.b16 {%0,%1,%2,%3}, [%4];"
                 : "=r"(r[0]), "=r"(r[1]), "=r"(r[2]), "=r"(r[3]) : "r"(a));
}
__device__ __forceinline__ void ldsm_x4_t(uint32_t* r, uint32_t a) {
    asm volatile("ldmatrix.sync.aligned.m8n8.x4.trans.shared.b16 {%0,%1,%2,%3}, [%4];"
                 : "=r"(r[0]), "=r"(r[1]), "=r"(r[2]), "=r"(r[3]) : "r"(a));
}

__device__ __forceinline__ void cp16(uint32_t d, const void* g) {
    asm volatile("cp.async.cg.shared.global [%0], [%1], 16;" :: "r"(d), "l"(g));
}
#define CP_COMMIT() asm volatile("cp.async.commit_group;" ::: "memory")
#define CP_WAIT0()  asm volatile("cp.async.wait_group 0;" ::: "memory")
#define CP_WAIT1()  asm volatile("cp.async.wait_group 1;" ::: "memory")

__device__ __forceinline__ uint32_t pack2f(float a, float b) {
    __half2 t = __floats2half2_rn(a, b);     // single F2FP.PACK
    return *reinterpret_cast<uint32_t*>(&t);
}

// =====================================================================
// Fused split kernel: X + all weights -> fp16.
// =====================================================================
__global__ void __launch_bounds__(256) split_all(
    const float* __restrict__ X,  const float* __restrict__ Wq,
    const float* __restrict__ Wk, const float* __restrict__ Wv,
    const float* __restrict__ Wo)
{
    const int i = blockIdx.x * blockDim.x + threadIdx.x;   // float4 index
    const float* src; __half* hi; int base;
    if (i < (1 << 20)) {
        src = X; hi = g_Xh; base = i;
    } else {
        const int r = i - (1 << 20);
        const int seg = r >> 18;
        base = r & ((1 << 18) - 1);
        switch (seg) {
            case 0:  src = Wq; hi = g_Wqh; break;
            case 1:  src = Wk; hi = g_Wkh; break;
            case 2:  src = Wv; hi = g_Wvh; break;
            default: src = Wo; hi = g_Woh; break;
        }
    }
    const float4 v = *(const float4*)(src + (size_t)base * 4);
    uint2 hh;
    hh.x = pack2f(v.x, v.y);
    hh.y = pack2f(v.z, v.w);
    *(uint2*)(hi + (size_t)base * 4) = hh;
}

// =====================================================================
// GEMM: C[128x128] = A * B^T + bias, fp16 mma.sync, K-stage 64.
// 256 thr, 8 warps (4m x 2n), cp.async triple buffer, 16 stages,
// one __syncthreads per stage. smem row = 64 fp16 + 16B pad = 144B.
// =====================================================================
#define GROW   144
#define GTILE  (128 * GROW)    // 18432: one [128 x 64] fp16 tile
#define GSTAGE (2 * GTILE)     // A, B = 36864
#define GEMM_SMEM (3 * GSTAGE) // 110592
#define NSTAGES (En / 64)      // 16

__device__ __forceinline__ void gemm_prefetch(
    uint32_t sbs, const __half* pA0, const __half* pB0, int k0, int tid)
{
    #pragma unroll
    for (int t = 0; t < 2; t++) {
        const __half* s = (t == 0) ? pA0 : pB0;
        #pragma unroll
        for (int i = 0; i < 4; i++) {
            int cc  = i * 256 + tid;       // 0..1023
            int row = cc >> 3, seg = cc & 7;
            cp16(sbs + t * GTILE + row * GROW + seg * 16,
                 s + (size_t)row * En + k0 + seg * 8);
        }
    }
}

__device__ __forceinline__ void gemm_core(
    const __half* __restrict__ Ah, const __half* __restrict__ Bh,
    const float* __restrict__ bias, float* __restrict__ outF,
    __half* __restrict__ outH, float outScale)
{
    extern __shared__ char smc[];
    const uint32_t sb = smem_u32(smc);
    const int tid = threadIdx.x, lane = tid & 31, wid = tid >> 5;
    const int wm = wid & 3, wn = wid >> 2;
    const int rowBase = blockIdx.y * 128, colBase = blockIdx.x * 128;

    const __half* pA0 = Ah + (size_t)rowBase * En;
    const __half* pB0 = Bh + (size_t)colBase * En;

    float acc[2][8][4];
    #pragma unroll
    for (int i = 0; i < 2; i++)
        #pragma unroll
        for (int j = 0; j < 8; j++)
            #pragma unroll
            for (int e = 0; e < 4; e++) acc[i][j][e] = 0.f;

    gemm_prefetch(sb, pA0, pB0, 0, tid);
    CP_COMMIT();
    gemm_prefetch(sb + GSTAGE, pA0, pB0, 64, tid);
    CP_COMMIT();

    const uint32_t aoff = (lane & 15) * GROW + (lane >> 4) * 16;
    const uint32_t boff = (((lane & 16) >> 1) + (lane & 7)) * GROW
                        + ((lane & 8) ? 16 : 0);

    uint32_t bufc = 0, bufp = 2;   // compute buf, prefetch buf (mod-3)
    for (int st = 0; st < NSTAGES; st++) {
        CP_WAIT1();          // stage st landed
        __syncthreads();     // all readers of buf[bufp] done
        if (st + 2 < NSTAGES) {
            gemm_prefetch(sb + bufp * GSTAGE, pA0, pB0, (st + 2) * 64, tid);
            CP_COMMIT();
        }
        const uint32_t s0 = sb + bufc * GSTAGE;
        bufc = (bufc == 2) ? 0 : bufc + 1;
        bufp = (bufp == 2) ? 0 : bufp + 1;
        const uint32_t aH = s0, bH = s0 + GTILE;

        #pragma unroll
        for (int kk = 0; kk < 4; kk++) {
            uint32_t ah[2][4], bh4[4][4];
            #pragma unroll
            for (int mi = 0; mi < 2; mi++)
                ldsm_x4(ah[mi], aH + (wm * 32 + mi * 16) * GROW + aoff + kk * 32);
            #pragma unroll
            for (int n4 = 0; n4 < 4; n4++)
                ldsm_x4(bh4[n4], bH + (wn * 64 + n4 * 16) * GROW + boff + kk * 32);
            #pragma unroll
            for (int mi = 0; mi < 2; mi++)
                #pragma unroll
                for (int nj = 0; nj < 8; nj++)
                    mma_f16(acc[mi][nj], ah[mi], &bh4[nj >> 1][(nj & 1) * 2]);
        }
    }

    // epilogue
    #pragma unroll
    for (int mi = 0; mi < 2; mi++) {
        const int rb = rowBase + wm * 32 + mi * 16 + (lane >> 2);
        #pragma unroll
        for (int half = 0; half < 2; half++) {
            const size_t r = (size_t)(rb + half * 8);
            #pragma unroll
            for (int nj = 0; nj < 8; nj++) {
                const int col = colBase + wn * 64 + nj * 8 + (lane & 3) * 2;
                float v0 = (acc[mi][nj][half * 2 + 0] + bias[col]) * outScale;
                float v1 = (acc[mi][nj][half * 2 + 1] + bias[col + 1]) * outScale;
                if (outF) {
                    *(float2*)&outF[r * En + col] = make_float2(v0, v1);
                } else {
                    *(uint32_t*)&outH[r * En + col] = pack2f(v0, v1);
                }
            }
        }
    }
}

__global__ void __launch_bounds__(256, 2) gemm_qkv(
    const float* bq, const float* bk, const float* bv)
{
    if (blockIdx.z == 0)
        gemm_core(g_Xh, g_Wqh, bq, nullptr, g_Qh, 0.125f);
    else if (blockIdx.z == 1)
        gemm_core(g_Xh, g_Wkh, bk, nullptr, g_Kh, 1.0f);
    else
        gemm_core(g_Xh, g_Wvh, bv, nullptr, g_Vh, 1.0f);
}

__global__ void __launch_bounds__(256, 2) gemm_out(const float* bo, float* out)
{
    gemm_core(g_Ah, g_Woh, bo, out, nullptr, 1.0f);
}

// =====================================================================
// Flash attention (causal) via mma.sync fp16. Q pre-scaled by 1/8.
// S = Qh*Kh;  O = Ph*Vh. KV stage: 2 tiles [64x64] fp16, row 144B.
// Triple buffer, one __syncthreads per key tile. 2 CTAs/SM.
// =====================================================================
#define KVTILE  (64 * 144)     // 9216
#define KVSTAGE (2 * KVTILE)   // 18432
#define FL_SMEM (3 * KVSTAGE)  // 55296

__device__ __forceinline__ void kv_prefetch(
    uint32_t sbs, int kt2, const __half* Kh, const __half* Vh, int tid)
{
    const size_t rowoff = (size_t)kt2 * 64;
    #pragma unroll
    for (int t = 0; t < 2; t++) {
        const __half* src = (t == 0) ? Kh : Vh;
        #pragma unroll
        for (int i = 0; i < 2; i++) {
            int cc  = i * 256 + tid;     // 0..511
            int row = cc >> 3, seg = cc & 7;
            cp16(sbs + t * KVTILE + row * 144 + seg * 16,
                 src + (rowoff + row) * En + seg * 8);
        }
    }
}

__global__ void __launch_bounds__(256, 2) flash_mma()
{
    extern __shared__ char smc[];
    const uint32_t sb = smem_u32(smc);
    const int tid = threadIdx.x, lane = tid & 31, wp = tid >> 5;
    const int g = lane >> 2, tg = lane & 3;
    const int qt = (int)gridDim.x - 1 - (int)blockIdx.x;   // big tiles first
    const int bh = blockIdx.y, bb = bh >> 4, hh = bh & 15;

    const size_t headoff = (size_t)bb * Tn * En + hh * HSn;
    const __half* Kh = g_Kh + headoff;
    const __half* Vh = g_Vh + headoff;

    const int nk = 2 * (qt + 1);   // always >= 2

    kv_prefetch(sb, 0, Kh, Vh, tid);
    CP_COMMIT();
    kv_prefetch(sb + KVSTAGE, 1, Kh, Vh, tid);
    CP_COMMIT();

    // Q fragments (fp16), loaded straight from gmem in frag layout
    uint32_t qh[4][4];
    {
        const size_t q0 = (size_t)(bb * Tn + qt * 128 + wp * 16 + g) * En
                        + hh * HSn;
        const size_t q1 = q0 + (size_t)8 * En;
        #pragma unroll
        for (int kk = 0; kk < 4; kk++) {
            const int c0 = kk * 16 + tg * 2, c1 = c0 + 8;
            qh[kk][0] = *(const uint32_t*)&g_Qh[q0 + c0];
            qh[kk][1] = *(const uint32_t*)&g_Qh[q1 + c0];
            qh[kk][2] = *(const uint32_t*)&g_Qh[q0 + c1];
            qh[kk][3] = *(const uint32_t*)&g_Qh[q1 + c1];
        }
    }

    float o[8][4];
    #pragma unroll
    for (int i = 0; i < 8; i++)
        #pragma unroll
        for (int e = 0; e < 4; e++) o[i][e] = 0.f;
    float m0 = -1e30f, m1 = -1e30f, l0 = 0.f, l1 = 0.f;
    const int qrow0 = qt * 128 + wp * 16 + g, qrow1 = qrow0 + 8;

    const uint32_t kboff = (((lane & 16) >> 1) + (lane & 7)) * 144
                         + ((lane & 8) ? 16 : 0);

    uint32_t bufc = 0, bufp = 2;
    for (int kt = 0; kt < nk; kt++) {
        CP_WAIT1();
        __syncthreads();
        if (kt + 2 < nk) {
            kv_prefetch(sb + bufp * KVSTAGE, kt + 2, Kh, Vh, tid);
            CP_COMMIT();
        }
        const uint32_t s0 = sb + bufc * KVSTAGE;
        bufc = (bufc == 2) ? 0 : bufc + 1;
        bufp = (bufp == 2) ? 0 : bufp + 1;
        const uint32_t kmh = s0, vmh = s0 + KVTILE;

        // ---- S = Qh Kh^T, 8 n8-tiles of 64 keys
        float s[8][4];
        #pragma unroll
        for (int i = 0; i < 8; i++)
            #pragma unroll
            for (int e = 0; e < 4; e++) s[i][e] = 0.f;

        #pragma unroll
        for (int kk = 0; kk < 4; kk++) {
            uint32_t kbh[4][4];
            #pragma unroll
            for (int n4 = 0; n4 < 4; n4++)
                ldsm_x4(kbh[n4], kmh + n4 * 16 * 144 + kboff + kk * 32);
            #pragma unroll
            for (int nj = 0; nj < 8; nj++)
                mma_f16(s[nj], qh[kk], &kbh[nj >> 1][(nj & 1) * 2]);
        }

        // ---- causal mask (diagonal tiles only)
        if (kt * 64 + 63 > qrow0) {
            #pragma unroll
            for (int nj = 0; nj < 8; nj++)
                #pragma unroll
                for (int e = 0; e < 4; e++) {
                    const int key = kt * 64 + nj * 8 + tg * 2 + (e & 1);
                    const int qr  = (e < 2) ? qrow0 : qrow1;
                    if (key > qr) s[nj][e] = -1e30f;
                }
        }

        // ---- online softmax (rows g and g+8)
        float mx0 = -1e30f, mx1 = -1e30f;
        #pragma unroll
        for (int nj = 0; nj < 8; nj++) {
            mx0 = fmaxf(mx0, fmaxf(s[nj][0], s[nj][1]));
            mx1 = fmaxf(mx1, fmaxf(s[nj][2], s[nj][3]));
        }
        mx0 = fmaxf(mx0, __shfl_xor_sync(0xffffffffu, mx0, 1));
        mx0 = fmaxf(mx0, __shfl_xor_sync(0xffffffffu, mx0, 2));
        mx1 = fmaxf(mx1, __shfl_xor_sync(0xffffffffu, mx1, 1));
        mx1 = fmaxf(mx1, __shfl_xor_sync(0xffffffffu, mx1, 2));
        const float mn0 = fmaxf(m0, mx0), mn1 = fmaxf(m1, mx1);
        const float a0 = __expf(m0 - mn0), a1 = __expf(m1 - mn1);
        m0 = mn0; m1 = mn1;
        float su0 = 0.f, su1 = 0.f;
        #pragma unroll
        for (int nj = 0; nj < 8; nj++) {
            s[nj][0] = __expf(s[nj][0] - mn0); su0 += s[nj][0];
            s[nj][1] = __expf(s[nj][1] - mn0); su0 += s[nj][1];
            s[nj][2] = __expf(s[nj][2] - mn1); su1 += s[nj][2];
            s[nj][3] = __expf(s[nj][3] - mn1); su1 += s[nj][3];
        }
        su0 += __shfl_xor_sync(0xffffffffu, su0, 1);
        su0 += __shfl_xor_sync(0xffffffffu, su0, 2);
        su1 += __shfl_xor_sync(0xffffffffu, su1, 1);
        su1 += __shfl_xor_sync(0xffffffffu, su1, 2);
        l0 = l0 * a0 + su0; l1 = l1 * a1 + su1;
        #pragma unroll
        for (int nj = 0; nj < 8; nj++) {
            o[nj][0] *= a0; o[nj][1] *= a0; o[nj][2] *= a1; o[nj][3] *= a1;
        }

        // ---- O += Ph Vh
        #pragma unroll
        for (int kk = 0; kk < 4; kk++) {
            uint32_t pah[4];
            {
                const float* p0 = s[2 * kk];
                const float* p1 = s[2 * kk + 1];
                pah[0] = pack2f(p0[0], p0[1]);
                pah[1] = pack2f(p0[2], p0[3]);
                pah[2] = pack2f(p1[0], p1[1]);
                pah[3] = pack2f(p1[2], p1[3]);
            }
            uint32_t vbh[4][4];
            const uint32_t voff = (kk * 16 + (lane & 15)) * 144
                                + ((lane & 16) ? 16 : 0);
            #pragma unroll
            for (int nb = 0; nb < 4; nb++)
                ldsm_x4_t(vbh[nb], vmh + voff + nb * 32);
            #pragma unroll
            for (int nd = 0; nd < 8; nd++)
                mma_f16(o[nd], pah, &vbh[nd >> 1][(nd & 1) * 2]);
        }
    }

    // ---- epilogue: normalize, fp16 store into g_Ah
    const float i0 = 1.f / l0, i1 = 1.f / l1;
    const size_t r0 = (size_t)(bb * Tn + qrow0) * En + hh * HSn;
    const size_t r1 = r0 + (size_t)8 * En;
    #pragma unroll
    for (int nd = 0; nd < 8; nd++) {
        const int col = nd * 8 + tg * 2;
        *(uint32_t*)&g_Ah[r0 + col] = pack2f(o[nd][0] * i0, o[nd][1] * i0);
        *(uint32_t*)&g_Ah[r1 + col] = pack2f(o[nd][2] * i1, o[nd][3] * i1);
    }
}

// =====================================================================
extern "C" void kernel_launch(void* const* d_in, const int* in_sizes, int n_in,
                              void* d_out, int out_size)
{
    (void)in_sizes; (void)n_in; (void)out_size;
    const float* X  = (const float*)d_in[0];
    const float* Wq = (const float*)d_in[1];
    const float* bq = (const float*)d_in[2];
    const float* Wk = (const float*)d_in[3];
    const float* bk = (const float*)d_in[4];
    const float* Wv = (const float*)d_in[5];
    const float* bv = (const float*)d_in[6];
    const float* Wo = (const float*)d_in[7];
    const float* bo = (const float*)d_in[8];
    float* out = (float*)d_out;

    cudaFuncSetAttribute(gemm_qkv,
                         cudaFuncAttributeMaxDynamicSharedMemorySize, GEMM_SMEM);
    cudaFuncSetAttribute(gemm_out,
                         cudaFuncAttributeMaxDynamicSharedMemorySize, GEMM_SMEM);
    cudaFuncSetAttribute(flash_mma,
                         cudaFuncAttributeMaxDynamicSharedMemorySize, FL_SMEM);

    dim3 blk(256);
    split_all<<<8192, 256>>>(X, Wq, Wk, Wv, Wo);
    gemm_qkv<<<dim3(En / 128, Mn / 128, 3), blk, GEMM_SMEM>>>(bq, bk, bv);
    flash_mma<<<dim3(Tn / 128, Bn * NHn), blk, FL_SMEM>>>();
    gemm_out<<<dim3(En / 128, Mn / 128), blk, GEMM_SMEM>>>(bo, out);
}

// round 11
// speedup vs baseline: 2.6159x; 1.0290x over previous
#include <cuda_runtime.h>
#include <cuda_fp16.h>
#include <cstdint>

// Problem constants
#define Bn  2
#define Tn  2048
#define En  1024
#define NHn 16
#define HSn 64
#define Mn  (Bn * Tn)        // 4096 token rows

// ---------------- scratch (device globals; no allocation) ----------------
__device__ __half g_Xh[(size_t)Mn * En];
__device__ __half g_Wqh[(size_t)En * En];
__device__ __half g_Wkh[(size_t)En * En];
__device__ __half g_Wvh[(size_t)En * En];
__device__ __half g_Woh[(size_t)En * En];
__device__ __half g_Qh[(size_t)Mn * En];   // pre-scaled by 1/8
__device__ __half g_Kh[(size_t)Mn * En];
__device__ __half g_Vh[(size_t)Mn * En];
__device__ __half g_Ah[(size_t)Mn * En];

// =====================================================================
// Baseline-PTX helpers
// =====================================================================
__device__ __forceinline__ uint32_t smem_u32(const void* p) {
    uint32_t a;
    asm("{ .reg .u64 t; cvta.to.shared.u64 t, %1; cvt.u32.u64 %0, t; }"
        : "=r"(a) : "l"(p));
    return a;
}

__device__ __forceinline__ void mma_f16(float* d, const uint32_t* a,
                                        const uint32_t* b) {
    asm volatile(
        "mma.sync.aligned.m16n8k16.row.col.f32.f16.f16.f32 "
        "{%0,%1,%2,%3}, {%4,%5,%6,%7}, {%8,%9}, {%0,%1,%2,%3};\n"
        : "+f"(d[0]), "+f"(d[1]), "+f"(d[2]), "+f"(d[3])
        : "r"(a[0]), "r"(a[1]), "r"(a[2]), "r"(a[3]), "r"(b[0]), "r"(b[1]));
}

__device__ __forceinline__ void ldsm_x4(uint32_t* r, uint32_t a) {
    asm volatile("ldmatrix.sync.aligned.m8n8.x4.shared.b16 {%0,%1,%2,%3}, [%4];"
                 : "=r"(r[0]), "=r"(r[1]), "=r"(r[2]), "=r"(r[3]) : "r"(a));
}
__device__ __forceinline__ void ldsm_x4_t(uint32_t* r, uint32_t a) {
    asm volatile("ldmatrix.sync.aligned.m8n8.x4.trans.shared.b16 {%0,%1,%2,%3}, [%4];"
                 : "=r"(r[0]), "=r"(r[1]), "=r"(r[2]), "=r"(r[3]) : "r"(a));
}

__device__ __forceinline__ void cp16(uint32_t d, const void* g) {
    asm volatile("cp.async.cg.shared.global [%0], [%1], 16;" :: "r"(d), "l"(g));
}
#define CP_COMMIT() asm volatile("cp.async.commit_group;" ::: "memory")
#define CP_WAIT0()  asm volatile("cp.async.wait_group 0;" ::: "memory")
#define CP_WAIT1()  asm volatile("cp.async.wait_group 1;" ::: "memory")

__device__ __forceinline__ uint32_t pack2f(float a, float b) {
    __half2 t = __floats2half2_rn(a, b);     // single F2FP.PACK
    return *reinterpret_cast<uint32_t*>(&t);
}

// packed fp16 2^x (MUFU, 2 lanes per op)
__device__ __forceinline__ uint32_t h2exp2u(uint32_t x) {
    uint32_t r;
    asm("ex2.approx.f16x2 %0, %1;" : "=r"(r) : "r"(x));
    return r;
}

// =====================================================================
// Fused split kernel: X + all weights -> fp16.
// =====================================================================
__global__ void __launch_bounds__(256) split_all(
    const float* __restrict__ X,  const float* __restrict__ Wq,
    const float* __restrict__ Wk, const float* __restrict__ Wv,
    const float* __restrict__ Wo)
{
    const int i = blockIdx.x * blockDim.x + threadIdx.x;   // float4 index
    const float* src; __half* hi; int base;
    if (i < (1 << 20)) {
        src = X; hi = g_Xh; base = i;
    } else {
        const int r = i - (1 << 20);
        const int seg = r >> 18;
        base = r & ((1 << 18) - 1);
        switch (seg) {
            case 0:  src = Wq; hi = g_Wqh; break;
            case 1:  src = Wk; hi = g_Wkh; break;
            case 2:  src = Wv; hi = g_Wvh; break;
            default: src = Wo; hi = g_Woh; break;
        }
    }
    const float4 v = *(const float4*)(src + (size_t)base * 4);
    uint2 hh;
    hh.x = pack2f(v.x, v.y);
    hh.y = pack2f(v.z, v.w);
    *(uint2*)(hi + (size_t)base * 4) = hh;
}

// =====================================================================
// GEMM: C[128x128] = A * B^T + bias, fp16 mma.sync, K-stage 64.
// 256 thr, 8 warps (4m x 2n), cp.async triple buffer, 16 stages,
// one __syncthreads per stage. smem row = 64 fp16 + 16B pad = 144B.
// =====================================================================
#define GROW   144
#define GTILE  (128 * GROW)    // 18432: one [128 x 64] fp16 tile
#define GSTAGE (2 * GTILE)     // A, B = 36864
#define GEMM_SMEM (3 * GSTAGE) // 110592
#define NSTAGES (En / 64)      // 16

__device__ __forceinline__ void gemm_prefetch(
    uint32_t sbs, const __half* pA0, const __half* pB0, int k0, int tid)
{
    #pragma unroll
    for (int t = 0; t < 2; t++) {
        const __half* s = (t == 0) ? pA0 : pB0;
        #pragma unroll
        for (int i = 0; i < 4; i++) {
            int cc  = i * 256 + tid;       // 0..1023
            int row = cc >> 3, seg = cc & 7;
            cp16(sbs + t * GTILE + row * GROW + seg * 16,
                 s + (size_t)row * En + k0 + seg * 8);
        }
    }
}

__device__ __forceinline__ void gemm_core(
    const __half* __restrict__ Ah, const __half* __restrict__ Bh,
    const float* __restrict__ bias, float* __restrict__ outF,
    __half* __restrict__ outH, float outScale)
{
    extern __shared__ char smc[];
    const uint32_t sb = smem_u32(smc);
    const int tid = threadIdx.x, lane = tid & 31, wid = tid >> 5;
    const int wm = wid & 3, wn = wid >> 2;
    const int rowBase = blockIdx.y * 128, colBase = blockIdx.x * 128;

    const __half* pA0 = Ah + (size_t)rowBase * En;
    const __half* pB0 = Bh + (size_t)colBase * En;

    float acc[2][8][4];
    #pragma unroll
    for (int i = 0; i < 2; i++)
        #pragma unroll
        for (int j = 0; j < 8; j++)
            #pragma unroll
            for (int e = 0; e < 4; e++) acc[i][j][e] = 0.f;

    gemm_prefetch(sb, pA0, pB0, 0, tid);
    CP_COMMIT();
    gemm_prefetch(sb + GSTAGE, pA0, pB0, 64, tid);
    CP_COMMIT();

    const uint32_t aoff = (lane & 15) * GROW + (lane >> 4) * 16;
    const uint32_t boff = (((lane & 16) >> 1) + (lane & 7)) * GROW
                        + ((lane & 8) ? 16 : 0);

    uint32_t bufc = 0, bufp = 2;   // compute buf, prefetch buf (mod-3)
    for (int st = 0; st < NSTAGES; st++) {
        CP_WAIT1();          // stage st landed
        __syncthreads();     // all readers of buf[bufp] done
        if (st + 2 < NSTAGES) {
            gemm_prefetch(sb + bufp * GSTAGE, pA0, pB0, (st + 2) * 64, tid);
            CP_COMMIT();
        }
        const uint32_t s0 = sb + bufc * GSTAGE;
        bufc = (bufc == 2) ? 0 : bufc + 1;
        bufp = (bufp == 2) ? 0 : bufp + 1;
        const uint32_t aH = s0, bH = s0 + GTILE;

        #pragma unroll
        for (int kk = 0; kk < 4; kk++) {
            uint32_t ah[2][4], bh4[4][4];
            #pragma unroll
            for (int mi = 0; mi < 2; mi++)
                ldsm_x4(ah[mi], aH + (wm * 32 + mi * 16) * GROW + aoff + kk * 32);
            #pragma unroll
            for (int n4 = 0; n4 < 4; n4++)
                ldsm_x4(bh4[n4], bH + (wn * 64 + n4 * 16) * GROW + boff + kk * 32);
            #pragma unroll
            for (int mi = 0; mi < 2; mi++)
                #pragma unroll
                for (int nj = 0; nj < 8; nj++)
                    mma_f16(acc[mi][nj], ah[mi], &bh4[nj >> 1][(nj & 1) * 2]);
        }
    }

    // epilogue
    #pragma unroll
    for (int mi = 0; mi < 2; mi++) {
        const int rb = rowBase + wm * 32 + mi * 16 + (lane >> 2);
        #pragma unroll
        for (int half = 0; half < 2; half++) {
            const size_t r = (size_t)(rb + half * 8);
            #pragma unroll
            for (int nj = 0; nj < 8; nj++) {
                const int col = colBase + wn * 64 + nj * 8 + (lane & 3) * 2;
                float v0 = (acc[mi][nj][half * 2 + 0] + bias[col]) * outScale;
                float v1 = (acc[mi][nj][half * 2 + 1] + bias[col + 1]) * outScale;
                if (outF) {
                    *(float2*)&outF[r * En + col] = make_float2(v0, v1);
                } else {
                    *(uint32_t*)&outH[r * En + col] = pack2f(v0, v1);
                }
            }
        }
    }
}

__global__ void __launch_bounds__(256, 2) gemm_qkv(
    const float* bq, const float* bk, const float* bv)
{
    if (blockIdx.z == 0)
        gemm_core(g_Xh, g_Wqh, bq, nullptr, g_Qh, 0.125f);
    else if (blockIdx.z == 1)
        gemm_core(g_Xh, g_Wkh, bk, nullptr, g_Kh, 1.0f);
    else
        gemm_core(g_Xh, g_Wvh, bv, nullptr, g_Vh, 1.0f);
}

__global__ void __launch_bounds__(256, 2) gemm_out(const float* bo, float* out)
{
    gemm_core(g_Ah, g_Woh, bo, out, nullptr, 1.0f);
}

// =====================================================================
// Flash attention (causal) via mma.sync fp16. Q pre-scaled by 1/8.
// S = Qh*Kh;  P via ex2.approx.f16x2 (packed fp16, feeds PV directly);
// o-rescale skipped when running max unchanged (warp-uniform guard).
// KV stage: 2 tiles [64x64] fp16, row 144B. Triple buffer. 2 CTAs/SM.
// =====================================================================
#define KVTILE  (64 * 144)     // 9216
#define KVSTAGE (2 * KVTILE)   // 18432
#define FL_SMEM (3 * KVSTAGE)  // 55296

__device__ __forceinline__ void kv_prefetch(
    uint32_t sbs, int kt2, const __half* Kh, const __half* Vh, int tid)
{
    const size_t rowoff = (size_t)kt2 * 64;
    #pragma unroll
    for (int t = 0; t < 2; t++) {
        const __half* src = (t == 0) ? Kh : Vh;
        #pragma unroll
        for (int i = 0; i < 2; i++) {
            int cc  = i * 256 + tid;     // 0..511
            int row = cc >> 3, seg = cc & 7;
            cp16(sbs + t * KVTILE + row * 144 + seg * 16,
                 src + (rowoff + row) * En + seg * 8);
        }
    }
}

__global__ void __launch_bounds__(256, 2) flash_mma()
{
    extern __shared__ char smc[];
    const uint32_t sb = smem_u32(smc);
    const int tid = threadIdx.x, lane = tid & 31, wp = tid >> 5;
    const int g = lane >> 2, tg = lane & 3;
    const int qt = (int)gridDim.x - 1 - (int)blockIdx.x;   // big tiles first
    const int bh = blockIdx.y, bb = bh >> 4, hh = bh & 15;

    const size_t headoff = (size_t)bb * Tn * En + hh * HSn;
    const __half* Kh = g_Kh + headoff;
    const __half* Vh = g_Vh + headoff;

    const int nk = 2 * (qt + 1);   // always >= 2

    kv_prefetch(sb, 0, Kh, Vh, tid);
    CP_COMMIT();
    kv_prefetch(sb + KVSTAGE, 1, Kh, Vh, tid);
    CP_COMMIT();

    // Q fragments (fp16), loaded straight from gmem in frag layout
    uint32_t qh[4][4];
    {
        const size_t q0 = (size_t)(bb * Tn + qt * 128 + wp * 16 + g) * En
                        + hh * HSn;
        const size_t q1 = q0 + (size_t)8 * En;
        #pragma unroll
        for (int kk = 0; kk < 4; kk++) {
            const int c0 = kk * 16 + tg * 2, c1 = c0 + 8;
            qh[kk][0] = *(const uint32_t*)&g_Qh[q0 + c0];
            qh[kk][1] = *(const uint32_t*)&g_Qh[q1 + c0];
            qh[kk][2] = *(const uint32_t*)&g_Qh[q0 + c1];
            qh[kk][3] = *(const uint32_t*)&g_Qh[q1 + c1];
        }
    }

    float o[8][4];
    #pragma unroll
    for (int i = 0; i < 8; i++)
        #pragma unroll
        for (int e = 0; e < 4; e++) o[i][e] = 0.f;
    float m0 = -1e30f, m1 = -1e30f, l0 = 0.f, l1 = 0.f;
    const int qrow0 = qt * 128 + wp * 16 + g, qrow1 = qrow0 + 8;

    const uint32_t kboff = (((lane & 16) >> 1) + (lane & 7)) * 144
                         + ((lane & 8) ? 16 : 0);
    const float L2E = 1.4426950408889634f;

    uint32_t bufc = 0, bufp = 2;
    for (int kt = 0; kt < nk; kt++) {
        CP_WAIT1();
        __syncthreads();
        if (kt + 2 < nk) {
            kv_prefetch(sb + bufp * KVSTAGE, kt + 2, Kh, Vh, tid);
            CP_COMMIT();
        }
        const uint32_t s0 = sb + bufc * KVSTAGE;
        bufc = (bufc == 2) ? 0 : bufc + 1;
        bufp = (bufp == 2) ? 0 : bufp + 1;
        const uint32_t kmh = s0, vmh = s0 + KVTILE;

        // ---- S = Qh Kh^T, 8 n8-tiles of 64 keys
        float s[8][4];
        #pragma unroll
        for (int i = 0; i < 8; i++)
            #pragma unroll
            for (int e = 0; e < 4; e++) s[i][e] = 0.f;

        #pragma unroll
        for (int kk = 0; kk < 4; kk++) {
            uint32_t kbh[4][4];
            #pragma unroll
            for (int n4 = 0; n4 < 4; n4++)
                ldsm_x4(kbh[n4], kmh + n4 * 16 * 144 + kboff + kk * 32);
            #pragma unroll
            for (int nj = 0; nj < 8; nj++)
                mma_f16(s[nj], qh[kk], &kbh[nj >> 1][(nj & 1) * 2]);
        }

        // ---- causal mask (diagonal tiles only)
        if (kt * 64 + 63 > qrow0) {
            #pragma unroll
            for (int nj = 0; nj < 8; nj++)
                #pragma unroll
                for (int e = 0; e < 4; e++) {
                    const int key = kt * 64 + nj * 8 + tg * 2 + (e & 1);
                    const int qr  = (e < 2) ? qrow0 : qrow1;
                    if (key > qr) s[nj][e] = -1e30f;
                }
        }

        // ---- row max (rows g and g+8)
        float mx0 = -1e30f, mx1 = -1e30f;
        #pragma unroll
        for (int nj = 0; nj < 8; nj++) {
            mx0 = fmaxf(mx0, fmaxf(s[nj][0], s[nj][1]));
            mx1 = fmaxf(mx1, fmaxf(s[nj][2], s[nj][3]));
        }
        mx0 = fmaxf(mx0, __shfl_xor_sync(0xffffffffu, mx0, 1));
        mx0 = fmaxf(mx0, __shfl_xor_sync(0xffffffffu, mx0, 2));
        mx1 = fmaxf(mx1, __shfl_xor_sync(0xffffffffu, mx1, 1));
        mx1 = fmaxf(mx1, __shfl_xor_sync(0xffffffffu, mx1, 2));
        const float mn0 = fmaxf(m0, mx0), mn1 = fmaxf(m1, mx1);

        // ---- rescale o,l only if some lane's max changed (warp-uniform)
        if (__any_sync(0xffffffffu, (mn0 > m0) || (mn1 > m1))) {
            const float a0 = __expf(m0 - mn0), a1 = __expf(m1 - mn1);
            l0 *= a0; l1 *= a1;
            #pragma unroll
            for (int nj = 0; nj < 8; nj++) {
                o[nj][0] *= a0; o[nj][1] *= a0;
                o[nj][2] *= a1; o[nj][3] *= a1;
            }
        }
        m0 = mn0; m1 = mn1;

        // ---- P = 2^((s-m)*log2e) in packed fp16 (feeds PV directly)
        const float nb0 = -mn0 * L2E, nb1 = -mn1 * L2E;
        uint32_t ph[8][2];
        float su0 = 0.f, su1 = 0.f;
        #pragma unroll
        for (int nj = 0; nj < 8; nj++) {
            ph[nj][0] = h2exp2u(pack2f(fmaf(s[nj][0], L2E, nb0),
                                       fmaf(s[nj][1], L2E, nb0)));
            ph[nj][1] = h2exp2u(pack2f(fmaf(s[nj][2], L2E, nb1),
                                       fmaf(s[nj][3], L2E, nb1)));
            const float2 f0 = __half22float2(*(const __half2*)&ph[nj][0]);
            const float2 f1 = __half22float2(*(const __half2*)&ph[nj][1]);
            su0 += f0.x + f0.y;
            su1 += f1.x + f1.y;
        }
        su0 += __shfl_xor_sync(0xffffffffu, su0, 1);
        su0 += __shfl_xor_sync(0xffffffffu, su0, 2);
        su1 += __shfl_xor_sync(0xffffffffu, su1, 1);
        su1 += __shfl_xor_sync(0xffffffffu, su1, 2);
        l0 += su0; l1 += su1;

        // ---- O += Ph Vh (P fragments already packed)
        #pragma unroll
        for (int kk = 0; kk < 4; kk++) {
            uint32_t pah[4];
            pah[0] = ph[2 * kk][0];
            pah[1] = ph[2 * kk][1];
            pah[2] = ph[2 * kk + 1][0];
            pah[3] = ph[2 * kk + 1][1];
            uint32_t vbh[4][4];
            const uint32_t voff = (kk * 16 + (lane & 15)) * 144
                                + ((lane & 16) ? 16 : 0);
            #pragma unroll
            for (int nb = 0; nb < 4; nb++)
                ldsm_x4_t(vbh[nb], vmh + voff + nb * 32);
            #pragma unroll
            for (int nd = 0; nd < 8; nd++)
                mma_f16(o[nd], pah, &vbh[nd >> 1][(nd & 1) * 2]);
        }
    }

    // ---- epilogue: normalize, fp16 store into g_Ah
    const float i0 = 1.f / l0, i1 = 1.f / l1;
    const size_t r0 = (size_t)(bb * Tn + qrow0) * En + hh * HSn;
    const size_t r1 = r0 + (size_t)8 * En;
    #pragma unroll
    for (int nd = 0; nd < 8; nd++) {
        const int col = nd * 8 + tg * 2;
        *(uint32_t*)&g_Ah[r0 + col] = pack2f(o[nd][0] * i0, o[nd][1] * i0);
        *(uint32_t*)&g_Ah[r1 + col] = pack2f(o[nd][2] * i1, o[nd][3] * i1);
    }
}

// =====================================================================
extern "C" void kernel_launch(void* const* d_in, const int* in_sizes, int n_in,
                              void* d_out, int out_size)
{
    (void)in_sizes; (void)n_in; (void)out_size;
    const float* X  = (const float*)d_in[0];
    const float* Wq = (const float*)d_in[1];
    const float* bq = (const float*)d_in[2];
    const float* Wk = (const float*)d_in[3];
    const float* bk = (const float*)d_in[4];
    const float* Wv = (const float*)d_in[5];
    const float* bv = (const float*)d_in[6];
    const float* Wo = (const float*)d_in[7];
    const float* bo = (const float*)d_in[8];
    float* out = (float*)d_out;

    cudaFuncSetAttribute(gemm_qkv,
                         cudaFuncAttributeMaxDynamicSharedMemorySize, GEMM_SMEM);
    cudaFuncSetAttribute(gemm_out,
                         cudaFuncAttributeMaxDynamicSharedMemorySize, GEMM_SMEM);
    cudaFuncSetAttribute(flash_mma,
                         cudaFuncAttributeMaxDynamicSharedMemorySize, FL_SMEM);

    dim3 blk(256);
    split_all<<<8192, 256>>>(X, Wq, Wk, Wv, Wo);
    gemm_qkv<<<dim3(En / 128, Mn / 128, 3), blk, GEMM_SMEM>>>(bq, bk, bv);
    flash_mma<<<dim3(Tn / 128, Bn * NHn), blk, FL_SMEM>>>();
    gemm_out<<<dim3(En / 128, Mn / 128), blk, GEMM_SMEM>>>(bo, out);
}

// round 12
// speedup vs baseline: 2.6849x; 1.0264x over previous
#include <cuda_runtime.h>
#include <cuda_fp16.h>
#include <cstdint>

// Problem constants
#define Bn  2
#define Tn  2048
#define En  1024
#define NHn 16
#define HSn 64
#define Mn  (Bn * Tn)        // 4096 token rows

// ---------------- scratch (device globals; no allocation) ----------------
__device__ __half g_Xh[(size_t)Mn * En];
__device__ __half g_Wqh[(size_t)En * En];
__device__ __half g_Wkh[(size_t)En * En];
__device__ __half g_Wvh[(size_t)En * En];
__device__ __half g_Woh[(size_t)En * En];
__device__ __half g_Qh[(size_t)Mn * En];   // pre-scaled by 1/8
__device__ __half g_Kh[(size_t)Mn * En];
__device__ __half g_Vh[(size_t)Mn * En];
__device__ __half g_Ah[(size_t)Mn * En];

// =====================================================================
// Baseline-PTX helpers
// =====================================================================
__device__ __forceinline__ uint32_t smem_u32(const void* p) {
    uint32_t a;
    asm("{ .reg .u64 t; cvta.to.shared.u64 t, %1; cvt.u32.u64 %0, t; }"
        : "=r"(a) : "l"(p));
    return a;
}

__device__ __forceinline__ void mma_f16(float* d, const uint32_t* a,
                                        const uint32_t* b) {
    asm volatile(
        "mma.sync.aligned.m16n8k16.row.col.f32.f16.f16.f32 "
        "{%0,%1,%2,%3}, {%4,%5,%6,%7}, {%8,%9}, {%0,%1,%2,%3};\n"
        : "+f"(d[0]), "+f"(d[1]), "+f"(d[2]), "+f"(d[3])
        : "r"(a[0]), "r"(a[1]), "r"(a[2]), "r"(a[3]), "r"(b[0]), "r"(b[1]));
}

__device__ __forceinline__ void ldsm_x4(uint32_t* r, uint32_t a) {
    asm volatile("ldmatrix.sync.aligned.m8n8.x4.shared.b16 {%0,%1,%2,%3}, [%4];"
                 : "=r"(r[0]), "=r"(r[1]), "=r"(r[2]), "=r"(r[3]) : "r"(a));
}
__device__ __forceinline__ void ldsm_x4_t(uint32_t* r, uint32_t a) {
    asm volatile("ldmatrix.sync.aligned.m8n8.x4.trans.shared.b16 {%0,%1,%2,%3}, [%4];"
                 : "=r"(r[0]), "=r"(r[1]), "=r"(r[2]), "=r"(r[3]) : "r"(a));
}

__device__ __forceinline__ void cp16(uint32_t d, const void* g) {
    asm volatile("cp.async.cg.shared.global [%0], [%1], 16;" :: "r"(d), "l"(g));
}
#define CP_COMMIT() asm volatile("cp.async.commit_group;" ::: "memory")
#define CP_WAIT0()  asm volatile("cp.async.wait_group 0;" ::: "memory")
#define CP_WAIT1()  asm volatile("cp.async.wait_group 1;" ::: "memory")

__device__ __forceinline__ uint32_t pack2f(float a, float b) {
    __half2 t = __floats2half2_rn(a, b);     // single F2FP.PACK
    return *reinterpret_cast<uint32_t*>(&t);
}

// packed fp16 2^x
__device__ __forceinline__ uint32_t h2exp2u(uint32_t x) {
    uint32_t r;
    asm("ex2.approx.f16x2 %0, %1;" : "=r"(r) : "r"(x));
    return r;
}

// =====================================================================
// Fused split kernel: X + all weights -> fp16.
// =====================================================================
__global__ void __launch_bounds__(256) split_all(
    const float* __restrict__ X,  const float* __restrict__ Wq,
    const float* __restrict__ Wk, const float* __restrict__ Wv,
    const float* __restrict__ Wo)
{
    const int i = blockIdx.x * blockDim.x + threadIdx.x;   // float4 index
    const float* src; __half* hi; int base;
    if (i < (1 << 20)) {
        src = X; hi = g_Xh; base = i;
    } else {
        const int r = i - (1 << 20);
        const int seg = r >> 18;
        base = r & ((1 << 18) - 1);
        switch (seg) {
            case 0:  src = Wq; hi = g_Wqh; break;
            case 1:  src = Wk; hi = g_Wkh; break;
            case 2:  src = Wv; hi = g_Wvh; break;
            default: src = Wo; hi = g_Woh; break;
        }
    }
    const float4 v = *(const float4*)(src + (size_t)base * 4);
    uint2 hh;
    hh.x = pack2f(v.x, v.y);
    hh.y = pack2f(v.z, v.w);
    *(uint2*)(hi + (size_t)base * 4) = hh;
}

// =====================================================================
// GEMM: C[128x128] = A * B^T + bias, fp16 mma.sync, K-stage 64.
// 256 thr, 8 warps (4m x 2n), cp.async triple buffer, 16 stages,
// one __syncthreads per stage. smem row = 64 fp16 + 16B pad = 144B.
// =====================================================================
#define GROW   144
#define GTILE  (128 * GROW)    // 18432: one [128 x 64] fp16 tile
#define GSTAGE (2 * GTILE)     // A, B = 36864
#define GEMM_SMEM (3 * GSTAGE) // 110592
#define NSTAGES (En / 64)      // 16

__device__ __forceinline__ void gemm_prefetch(
    uint32_t sbs, const __half* pA0, const __half* pB0, int k0, int tid)
{
    #pragma unroll
    for (int t = 0; t < 2; t++) {
        const __half* s = (t == 0) ? pA0 : pB0;
        #pragma unroll
        for (int i = 0; i < 4; i++) {
            int cc  = i * 256 + tid;       // 0..1023
            int row = cc >> 3, seg = cc & 7;
            cp16(sbs + t * GTILE + row * GROW + seg * 16,
                 s + (size_t)row * En + k0 + seg * 8);
        }
    }
}

__device__ __forceinline__ void gemm_core(
    const __half* __restrict__ Ah, const __half* __restrict__ Bh,
    const float* __restrict__ bias, float* __restrict__ outF,
    __half* __restrict__ outH, float outScale)
{
    extern __shared__ char smc[];
    const uint32_t sb = smem_u32(smc);
    const int tid = threadIdx.x, lane = tid & 31, wid = tid >> 5;
    const int wm = wid & 3, wn = wid >> 2;
    const int rowBase = blockIdx.y * 128, colBase = blockIdx.x * 128;

    const __half* pA0 = Ah + (size_t)rowBase * En;
    const __half* pB0 = Bh + (size_t)colBase * En;

    float acc[2][8][4];
    #pragma unroll
    for (int i = 0; i < 2; i++)
        #pragma unroll
        for (int j = 0; j < 8; j++)
            #pragma unroll
            for (int e = 0; e < 4; e++) acc[i][j][e] = 0.f;

    gemm_prefetch(sb, pA0, pB0, 0, tid);
    CP_COMMIT();
    gemm_prefetch(sb + GSTAGE, pA0, pB0, 64, tid);
    CP_COMMIT();

    const uint32_t aoff = (lane & 15) * GROW + (lane >> 4) * 16;
    const uint32_t boff = (((lane & 16) >> 1) + (lane & 7)) * GROW
                        + ((lane & 8) ? 16 : 0);

    uint32_t bufc = 0, bufp = 2;   // compute buf, prefetch buf (mod-3)
    for (int st = 0; st < NSTAGES; st++) {
        CP_WAIT1();          // stage st landed
        __syncthreads();     // all readers of buf[bufp] done
        if (st + 2 < NSTAGES) {
            gemm_prefetch(sb + bufp * GSTAGE, pA0, pB0, (st + 2) * 64, tid);
            CP_COMMIT();
        }
        const uint32_t s0 = sb + bufc * GSTAGE;
        bufc = (bufc == 2) ? 0 : bufc + 1;
        bufp = (bufp == 2) ? 0 : bufp + 1;
        const uint32_t aH = s0, bH = s0 + GTILE;

        #pragma unroll
        for (int kk = 0; kk < 4; kk++) {
            uint32_t ah[2][4], bh4[4][4];
            #pragma unroll
            for (int mi = 0; mi < 2; mi++)
                ldsm_x4(ah[mi], aH + (wm * 32 + mi * 16) * GROW + aoff + kk * 32);
            #pragma unroll
            for (int n4 = 0; n4 < 4; n4++)
                ldsm_x4(bh4[n4], bH + (wn * 64 + n4 * 16) * GROW + boff + kk * 32);
            #pragma unroll
            for (int mi = 0; mi < 2; mi++)
                #pragma unroll
                for (int nj = 0; nj < 8; nj++)
                    mma_f16(acc[mi][nj], ah[mi], &bh4[nj >> 1][(nj & 1) * 2]);
        }
    }

    // epilogue
    #pragma unroll
    for (int mi = 0; mi < 2; mi++) {
        const int rb = rowBase + wm * 32 + mi * 16 + (lane >> 2);
        #pragma unroll
        for (int half = 0; half < 2; half++) {
            const size_t r = (size_t)(rb + half * 8);
            #pragma unroll
            for (int nj = 0; nj < 8; nj++) {
                const int col = colBase + wn * 64 + nj * 8 + (lane & 3) * 2;
                float v0 = (acc[mi][nj][half * 2 + 0] + bias[col]) * outScale;
                float v1 = (acc[mi][nj][half * 2 + 1] + bias[col + 1]) * outScale;
                if (outF) {
                    *(float2*)&outF[r * En + col] = make_float2(v0, v1);
                } else {
                    *(uint32_t*)&outH[r * En + col] = pack2f(v0, v1);
                }
            }
        }
    }
}

__global__ void __launch_bounds__(256, 2) gemm_qkv(
    const float* bq, const float* bk, const float* bv)
{
    if (blockIdx.z == 0)
        gemm_core(g_Xh, g_Wqh, bq, nullptr, g_Qh, 0.125f);
    else if (blockIdx.z == 1)
        gemm_core(g_Xh, g_Wkh, bk, nullptr, g_Kh, 1.0f);
    else
        gemm_core(g_Xh, g_Wvh, bv, nullptr, g_Vh, 1.0f);
}

__global__ void __launch_bounds__(256, 2) gemm_out(const float* bo, float* out)
{
    gemm_core(g_Ah, g_Woh, bo, out, nullptr, 1.0f);
}

// =====================================================================
// Flash attention (causal) via mma.sync fp16. Q pre-scaled by 1/8.
// S = Qh*Kh; P via ex2.approx.f16x2; row-sum l computed ON THE TENSOR
// PIPE as P @ ones (extra MMA per kk) -> no cvt/add/shuffle chain.
// KV stage: 2 tiles [64x64] fp16, row 144B. Triple buffer. 2 CTAs/SM.
// =====================================================================
#define KVTILE  (64 * 144)     // 9216
#define KVSTAGE (2 * KVTILE)   // 18432
#define FL_SMEM (3 * KVSTAGE)  // 55296

__device__ __forceinline__ void kv_prefetch(
    uint32_t sbs, int kt2, const __half* Kh, const __half* Vh, int tid)
{
    const size_t rowoff = (size_t)kt2 * 64;
    #pragma unroll
    for (int t = 0; t < 2; t++) {
        const __half* src = (t == 0) ? Kh : Vh;
        #pragma unroll
        for (int i = 0; i < 2; i++) {
            int cc  = i * 256 + tid;     // 0..511
            int row = cc >> 3, seg = cc & 7;
            cp16(sbs + t * KVTILE + row * 144 + seg * 16,
                 src + (rowoff + row) * En + seg * 8);
        }
    }
}

__global__ void __launch_bounds__(256, 2) flash_mma()
{
    extern __shared__ char smc[];
    const uint32_t sb = smem_u32(smc);
    const int tid = threadIdx.x, lane = tid & 31, wp = tid >> 5;
    const int g = lane >> 2, tg = lane & 3;
    const int qt = (int)gridDim.x - 1 - (int)blockIdx.x;   // big tiles first
    const int bh = blockIdx.y, bb = bh >> 4, hh = bh & 15;

    const size_t headoff = (size_t)bb * Tn * En + hh * HSn;
    const __half* Kh = g_Kh + headoff;
    const __half* Vh = g_Vh + headoff;

    const int nk = 2 * (qt + 1);   // always >= 2

    kv_prefetch(sb, 0, Kh, Vh, tid);
    CP_COMMIT();
    kv_prefetch(sb + KVSTAGE, 1, Kh, Vh, tid);
    CP_COMMIT();

    // Q fragments (fp16), loaded straight from gmem in frag layout
    uint32_t qh[4][4];
    {
        const size_t q0 = (size_t)(bb * Tn + qt * 128 + wp * 16 + g) * En
                        + hh * HSn;
        const size_t q1 = q0 + (size_t)8 * En;
        #pragma unroll
        for (int kk = 0; kk < 4; kk++) {
            const int c0 = kk * 16 + tg * 2, c1 = c0 + 8;
            qh[kk][0] = *(const uint32_t*)&g_Qh[q0 + c0];
            qh[kk][1] = *(const uint32_t*)&g_Qh[q1 + c0];
            qh[kk][2] = *(const uint32_t*)&g_Qh[q0 + c1];
            qh[kk][3] = *(const uint32_t*)&g_Qh[q1 + c1];
        }
    }

    float o[8][4];
    #pragma unroll
    for (int i = 0; i < 8; i++)
        #pragma unroll
        for (int e = 0; e < 4; e++) o[i][e] = 0.f;
    float la[4] = {0.f, 0.f, 0.f, 0.f};     // l accumulator (P @ ones)
    float m0 = -1e30f, m1 = -1e30f;
    const int qrow0 = qt * 128 + wp * 16 + g, qrow1 = qrow0 + 8;

    const uint32_t kboff = (((lane & 16) >> 1) + (lane & 7)) * 144
                         + ((lane & 8) ? 16 : 0);
    const float L2E = 1.4426950408889634f;
    const uint32_t onesb[2] = {0x3C003C00u, 0x3C003C00u};   // half2(1,1) x2

    uint32_t bufc = 0, bufp = 2;
    for (int kt = 0; kt < nk; kt++) {
        CP_WAIT1();
        __syncthreads();
        if (kt + 2 < nk) {
            kv_prefetch(sb + bufp * KVSTAGE, kt + 2, Kh, Vh, tid);
            CP_COMMIT();
        }
        const uint32_t s0 = sb + bufc * KVSTAGE;
        bufc = (bufc == 2) ? 0 : bufc + 1;
        bufp = (bufp == 2) ? 0 : bufp + 1;
        const uint32_t kmh = s0, vmh = s0 + KVTILE;

        // ---- S = Qh Kh^T, 8 n8-tiles of 64 keys
        float s[8][4];
        #pragma unroll
        for (int i = 0; i < 8; i++)
            #pragma unroll
            for (int e = 0; e < 4; e++) s[i][e] = 0.f;

        #pragma unroll
        for (int kk = 0; kk < 4; kk++) {
            uint32_t kbh[4][4];
            #pragma unroll
            for (int n4 = 0; n4 < 4; n4++)
                ldsm_x4(kbh[n4], kmh + n4 * 16 * 144 + kboff + kk * 32);
            #pragma unroll
            for (int nj = 0; nj < 8; nj++)
                mma_f16(s[nj], qh[kk], &kbh[nj >> 1][(nj & 1) * 2]);
        }

        // ---- causal mask (diagonal tiles only)
        if (kt * 64 + 63 > qrow0) {
            #pragma unroll
            for (int nj = 0; nj < 8; nj++)
                #pragma unroll
                for (int e = 0; e < 4; e++) {
                    const int key = kt * 64 + nj * 8 + tg * 2 + (e & 1);
                    const int qr  = (e < 2) ? qrow0 : qrow1;
                    if (key > qr) s[nj][e] = -1e30f;
                }
        }

        // ---- row max (rows g and g+8)
        float mx0 = -1e30f, mx1 = -1e30f;
        #pragma unroll
        for (int nj = 0; nj < 8; nj++) {
            mx0 = fmaxf(mx0, fmaxf(s[nj][0], s[nj][1]));
            mx1 = fmaxf(mx1, fmaxf(s[nj][2], s[nj][3]));
        }
        mx0 = fmaxf(mx0, __shfl_xor_sync(0xffffffffu, mx0, 1));
        mx0 = fmaxf(mx0, __shfl_xor_sync(0xffffffffu, mx0, 2));
        mx1 = fmaxf(mx1, __shfl_xor_sync(0xffffffffu, mx1, 1));
        mx1 = fmaxf(mx1, __shfl_xor_sync(0xffffffffu, mx1, 2));
        const float mn0 = fmaxf(m0, mx0), mn1 = fmaxf(m1, mx1);

        // ---- rescale o, la only if some lane's max changed (warp-uniform)
        if (__any_sync(0xffffffffu, (mn0 > m0) || (mn1 > m1))) {
            const float a0 = __expf(m0 - mn0), a1 = __expf(m1 - mn1);
            la[0] *= a0; la[2] *= a1;
            #pragma unroll
            for (int nj = 0; nj < 8; nj++) {
                o[nj][0] *= a0; o[nj][1] *= a0;
                o[nj][2] *= a1; o[nj][3] *= a1;
            }
        }
        m0 = mn0; m1 = mn1;

        // ---- P = 2^((s-m)*log2e) in packed fp16 (feeds PV directly)
        const float nb0 = -mn0 * L2E, nb1 = -mn1 * L2E;
        uint32_t ph[8][2];
        #pragma unroll
        for (int nj = 0; nj < 8; nj++) {
            ph[nj][0] = h2exp2u(pack2f(fmaf(s[nj][0], L2E, nb0),
                                       fmaf(s[nj][1], L2E, nb0)));
            ph[nj][1] = h2exp2u(pack2f(fmaf(s[nj][2], L2E, nb1),
                                       fmaf(s[nj][3], L2E, nb1)));
        }

        // ---- O += Ph Vh;  la += Ph @ ones (row sums on tensor pipe)
        #pragma unroll
        for (int kk = 0; kk < 4; kk++) {
            uint32_t pah[4];
            pah[0] = ph[2 * kk][0];
            pah[1] = ph[2 * kk][1];
            pah[2] = ph[2 * kk + 1][0];
            pah[3] = ph[2 * kk + 1][1];
            mma_f16(la, pah, onesb);           // row-sum MMA
            uint32_t vbh[4][4];
            const uint32_t voff = (kk * 16 + (lane & 15)) * 144
                                + ((lane & 16) ? 16 : 0);
            #pragma unroll
            for (int nb = 0; nb < 4; nb++)
                ldsm_x4_t(vbh[nb], vmh + voff + nb * 32);
            #pragma unroll
            for (int nd = 0; nd < 8; nd++)
                mma_f16(o[nd], pah, &vbh[nd >> 1][(nd & 1) * 2]);
        }
    }

    // ---- epilogue: normalize, fp16 store into g_Ah
    const float i0 = 1.f / la[0], i1 = 1.f / la[2];
    const size_t r0 = (size_t)(bb * Tn + qrow0) * En + hh * HSn;
    const size_t r1 = r0 + (size_t)8 * En;
    #pragma unroll
    for (int nd = 0; nd < 8; nd++) {
        const int col = nd * 8 + tg * 2;
        *(uint32_t*)&g_Ah[r0 + col] = pack2f(o[nd][0] * i0, o[nd][1] * i0);
        *(uint32_t*)&g_Ah[r1 + col] = pack2f(o[nd][2] * i1, o[nd][3] * i1);
    }
}

// =====================================================================
extern "C" void kernel_launch(void* const* d_in, const int* in_sizes, int n_in,
                              void* d_out, int out_size)
{
    (void)in_sizes; (void)n_in; (void)out_size;
    const float* X  = (const float*)d_in[0];
    const float* Wq = (const float*)d_in[1];
    const float* bq = (const float*)d_in[2];
    const float* Wk = (const float*)d_in[3];
    const float* bk = (const float*)d_in[4];
    const float* Wv = (const float*)d_in[5];
    const float* bv = (const float*)d_in[6];
    const float* Wo = (const float*)d_in[7];
    const float* bo = (const float*)d_in[8];
    float* out = (float*)d_out;

    cudaFuncSetAttribute(gemm_qkv,
                         cudaFuncAttributeMaxDynamicSharedMemorySize, GEMM_SMEM);
    cudaFuncSetAttribute(gemm_out,
                         cudaFuncAttributeMaxDynamicSharedMemorySize, GEMM_SMEM);
    cudaFuncSetAttribute(flash_mma,
                         cudaFuncAttributeMaxDynamicSharedMemorySize, FL_SMEM);

    dim3 blk(256);
    split_all<<<8192, 256>>>(X, Wq, Wk, Wv, Wo);
    gemm_qkv<<<dim3(En / 128, Mn / 128, 3), blk, GEMM_SMEM>>>(bq, bk, bv);
    flash_mma<<<dim3(Tn / 128, Bn * NHn), blk, FL_SMEM>>>();
    gemm_out<<<dim3(En / 128, Mn / 128), blk, GEMM_SMEM>>>(bo, out);
}